// round 3
// baseline (speedup 1.0000x reference)
#include <cuda_runtime.h>
#include <math.h>

#define N_ 100000
#define R_ 3
#define E_ 320000
#define TOTSEG (R_*N_)
#define TOTE (R_*E_)
#define NB_SCAN ((TOTSEG + 1023) / 1024)

__device__ float g_Wc_src[R_*128*128];
__device__ float g_Wc_dst[R_*128*128];
__device__ float g_bc_src[R_*128];
__device__ float g_bc_dst[R_*128];
__device__ float g_U[R_*128*4];
__device__ float g_V[R_*128*4];
__device__ float4 g_elb4[R_];
__device__ float4 g_erb4[R_];
__device__ float g_hs[(size_t)R_*N_*128];
__device__ float4 g_el4[R_*N_];
__device__ float4 g_er4[R_*N_];
__device__ int   g_cnt[TOTSEG];
__device__ int   g_rowptr[TOTSEG + 1];
__device__ int   g_cursor[TOTSEG];
__device__ int   g_blksum[NB_SCAN];
__device__ int   g_blkoff[NB_SCAN];
__device__ int   g_perm[TOTE];
__device__ float g_z[(size_t)R_*N_*128];
__device__ float g_wsum[R_];
__device__ float g_a[R_];

__device__ __forceinline__ unsigned long long pk(float x, float y) {
    unsigned long long r;
    asm("mov.b64 %0, {%1, %2};" : "=l"(r) : "f"(x), "f"(y));
    return r;
}
__device__ __forceinline__ void fma2(unsigned long long& d, unsigned long long a,
                                     unsigned long long b) {
    asm("fma.rn.f32x2 %0, %1, %2, %0;" : "+l"(d) : "l"(a), "l"(b));
}
__device__ __forceinline__ float2 upk(unsigned long long v) {
    float2 f;
    asm("mov.b64 {%0, %1}, %2;" : "=f"(f.x), "=f"(f.y) : "l"(v));
    return f;
}
__device__ __forceinline__ float tanha(float x) {
    float y; asm("tanh.approx.f32 %0, %1;" : "=f"(y) : "f"(x)); return y;
}
__device__ __forceinline__ float lrelu(float x) { return x > 0.f ? x : 0.2f * x; }
__device__ __forceinline__ float elu1(float x)  { return x > 0.f ? x : (__expf(x) - 1.f); }

// C = A(nrows x 128) @ W(128 x 128). MODE 0: C += bias, store.
// MODE 1: wsum[r] += sum_all tanh(C + b1[col]) * W2[col]
template <int MODE>
__global__ void __launch_bounds__(256)
gemm_tile(const float* __restrict__ A, long long astride, int nrows,
          const float* __restrict__ W, long long wstride,
          const float* __restrict__ bias,
          float* __restrict__ C, long long cstride,
          const float* __restrict__ W2) {
    int r = blockIdx.y;
    int row0 = blockIdx.x * 128;
    const float* Ar = A + (size_t)r * astride;
    const float* Wr = W + (size_t)r * wstride;

    __shared__ __align__(16) float sA[16][132];
    __shared__ __align__(16) float sB[16][128];
    __shared__ float sred[8];

    int tid = threadIdx.x, tx = tid & 15, ty = tid >> 4;

    unsigned long long acc[8][4];
#pragma unroll
    for (int i = 0; i < 8; i++)
#pragma unroll
        for (int p = 0; p < 4; p++) acc[i][p] = 0ull;

    for (int kk = 0; kk < 128; kk += 16) {
#pragma unroll
        for (int l = 0; l < 2; l++) {
            int q = tid + l * 256;
            int row = q >> 2, ks = (q & 3) * 4;
            float4 v = make_float4(0.f, 0.f, 0.f, 0.f);
            int grow = row0 + row;
            if (grow < nrows)
                v = *(const float4*)(Ar + (size_t)grow * 128 + kk + ks);
            sA[ks + 0][row] = v.x; sA[ks + 1][row] = v.y;
            sA[ks + 2][row] = v.z; sA[ks + 3][row] = v.w;
        }
#pragma unroll
        for (int l = 0; l < 2; l++) {
            int q = tid + l * 256;
            int k = q >> 5, c = (q & 31) * 4;
            *(float4*)&sB[k][c] = *(const float4*)(Wr + (size_t)(kk + k) * 128 + c);
        }
        __syncthreads();
#pragma unroll
        for (int k = 0; k < 16; k++) {
            float4 a0 = *(const float4*)&sA[k][ty * 8];
            float4 a1 = *(const float4*)&sA[k][ty * 8 + 4];
            float4 b0 = *(const float4*)&sB[k][tx * 8];
            float4 b1 = *(const float4*)&sB[k][tx * 8 + 4];
            unsigned long long pb0 = pk(b0.x, b0.y), pb1 = pk(b0.z, b0.w);
            unsigned long long pb2 = pk(b1.x, b1.y), pb3 = pk(b1.z, b1.w);
            float av[8] = {a0.x, a0.y, a0.z, a0.w, a1.x, a1.y, a1.z, a1.w};
#pragma unroll
            for (int i = 0; i < 8; i++) {
                unsigned long long pa = pk(av[i], av[i]);
                fma2(acc[i][0], pa, pb0); fma2(acc[i][1], pa, pb1);
                fma2(acc[i][2], pa, pb2); fma2(acc[i][3], pa, pb3);
            }
        }
        __syncthreads();
    }

    if (MODE == 0) {
        float* Cr = C + (size_t)r * cstride;
        int c0 = tx * 8;
        float bv[8];
#pragma unroll
        for (int j = 0; j < 8; j++) bv[j] = bias ? bias[c0 + j] : 0.f;
#pragma unroll
        for (int i = 0; i < 8; i++) {
            int grow = row0 + ty * 8 + i;
            if (grow >= nrows) continue;
            float o[8];
#pragma unroll
            for (int p = 0; p < 4; p++) {
                float2 v = upk(acc[i][p]);
                o[2 * p] = v.x + bv[2 * p]; o[2 * p + 1] = v.y + bv[2 * p + 1];
            }
            *(float4*)(Cr + (size_t)grow * 128 + c0) = make_float4(o[0], o[1], o[2], o[3]);
            *(float4*)(Cr + (size_t)grow * 128 + c0 + 4) = make_float4(o[4], o[5], o[6], o[7]);
        }
    } else {
        int c0 = tx * 8;
        float b1v[8], w2v[8];
#pragma unroll
        for (int j = 0; j < 8; j++) { b1v[j] = bias[c0 + j]; w2v[j] = W2[c0 + j]; }
        float s = 0.f;
#pragma unroll
        for (int i = 0; i < 8; i++) {
            int grow = row0 + ty * 8 + i;
            if (grow >= nrows) continue;
#pragma unroll
            for (int p = 0; p < 4; p++) {
                float2 v = upk(acc[i][p]);
                s += tanha(v.x + b1v[2 * p]) * w2v[2 * p];
                s += tanha(v.y + b1v[2 * p + 1]) * w2v[2 * p + 1];
            }
        }
#pragma unroll
        for (int o = 16; o; o >>= 1) s += __shfl_xor_sync(0xffffffffu, s, o);
        if ((tid & 31) == 0) sred[tid >> 5] = s;
        __syncthreads();
        if (tid == 0) {
            float t = 0.f;
#pragma unroll
            for (int j = 0; j < 8; j++) t += sred[j];
            atomicAdd(&g_wsum[r], t);
        }
    }
}

__global__ void prep_bias(const float* __restrict__ bt_src,
                          const float* __restrict__ bt_dst,
                          const float* __restrict__ Wg) {
    int t = blockIdx.x * blockDim.x + threadIdx.x;
    if (t >= R_ * 128) return;
    int r = t >> 7, c = t & 127;
    const float* Wgr = Wg + r * 128 * 128;
    float s1 = 0.f, s2 = 0.f;
    for (int h = 0; h < 128; h++) {
        float w = Wgr[h * 128 + c];
        s1 += bt_src[r * 128 + h] * w;
        s2 += bt_dst[h] * w;
    }
    g_bc_src[t] = s1; g_bc_dst[t] = s2;
}

__global__ void prep_uv(const float* __restrict__ attn_l,
                        const float* __restrict__ attn_r) {
    int r = blockIdx.x, k = threadIdx.x;
    const float* Wcs = g_Wc_src + r * 16384;
    const float* Wcd = g_Wc_dst + r * 16384;
    const float* al = attn_l + r * 128;
    const float* ar = attn_r + r * 128;
    float u[4] = {0, 0, 0, 0}, v[4] = {0, 0, 0, 0};
    for (int c = 0; c < 128; c++) {
        int h = c >> 5;
        u[h] += Wcs[k * 128 + c] * al[c];
        v[h] += Wcd[k * 128 + c] * ar[c];
    }
#pragma unroll
    for (int h = 0; h < 4; h++) {
        g_U[(r * 128 + k) * 4 + h] = u[h];
        g_V[(r * 128 + k) * 4 + h] = v[h];
    }
    if (k < 4) {
        float s = 0.f, s2 = 0.f;
        for (int d = 0; d < 32; d++) {
            int c = k * 32 + d;
            s += g_bc_src[r * 128 + c] * al[c];
            s2 += g_bc_dst[r * 128 + c] * ar[c];
        }
        ((float*)g_elb4)[r * 4 + k] = s;
        ((float*)g_erb4)[r * 4 + k] = s2;
    }
}

__global__ void attn_proj(const float* __restrict__ src_feats,
                          const float* __restrict__ dst_feat) {
    int gw = (blockIdx.x * 256 + threadIdx.x) >> 5;
    int lane = threadIdx.x & 31;
    if (gw >= N_) return;
    float4 dv = *(const float4*)(dst_feat + (size_t)gw * 128 + lane * 4);
    float dvv[4] = {dv.x, dv.y, dv.z, dv.w};
#pragma unroll
    for (int r = 0; r < R_; r++) {
        const float4* U4 = (const float4*)(g_U + r * 512);
        const float4* V4 = (const float4*)(g_V + r * 512);
        float4 sv = *(const float4*)(src_feats + ((size_t)r * N_ + gw) * 128 + lane * 4);
        float svv[4] = {sv.x, sv.y, sv.z, sv.w};
        float4 aE = make_float4(0, 0, 0, 0), aD = make_float4(0, 0, 0, 0);
#pragma unroll
        for (int i = 0; i < 4; i++) {
            float4 u = U4[lane * 4 + i];
            float4 w = V4[lane * 4 + i];
            aE.x += svv[i] * u.x; aE.y += svv[i] * u.y;
            aE.z += svv[i] * u.z; aE.w += svv[i] * u.w;
            aD.x += dvv[i] * w.x; aD.y += dvv[i] * w.y;
            aD.z += dvv[i] * w.z; aD.w += dvv[i] * w.w;
        }
#pragma unroll
        for (int o = 16; o; o >>= 1) {
            aE.x += __shfl_xor_sync(0xffffffffu, aE.x, o);
            aE.y += __shfl_xor_sync(0xffffffffu, aE.y, o);
            aE.z += __shfl_xor_sync(0xffffffffu, aE.z, o);
            aE.w += __shfl_xor_sync(0xffffffffu, aE.w, o);
            aD.x += __shfl_xor_sync(0xffffffffu, aD.x, o);
            aD.y += __shfl_xor_sync(0xffffffffu, aD.y, o);
            aD.z += __shfl_xor_sync(0xffffffffu, aD.z, o);
            aD.w += __shfl_xor_sync(0xffffffffu, aD.w, o);
        }
        if (lane == 0) {
            float4 eb = g_elb4[r], rb = g_erb4[r];
            g_el4[r * N_ + gw] = make_float4(aE.x + eb.x, aE.y + eb.y, aE.z + eb.z, aE.w + eb.w);
            g_er4[r * N_ + gw] = make_float4(aD.x + rb.x, aD.y + rb.y, aD.z + rb.z, aD.w + rb.w);
        }
    }
}

__global__ void zero_misc() {
    int t = blockIdx.x * 256 + threadIdx.x;
    if (t < TOTSEG) g_cnt[t] = 0;
    if (t < R_) g_wsum[t] = 0.f;
}
__global__ void count_k(const int* __restrict__ dst_idx) {
    int g = blockIdx.x * 256 + threadIdx.x;
    if (g >= TOTE) return;
    int r = g / E_;
    atomicAdd(&g_cnt[r * N_ + dst_idx[g]], 1);
}
__global__ void scan1_k() {
    __shared__ int sh[256];
    int b = blockIdx.x, t = threadIdx.x;
    int base = b * 1024 + t * 4;
    int v[4];
#pragma unroll
    for (int i = 0; i < 4; i++) v[i] = (base + i < TOTSEG) ? g_cnt[base + i] : 0;
    int s = v[0] + v[1] + v[2] + v[3];
    sh[t] = s;
    __syncthreads();
    for (int o = 1; o < 256; o <<= 1) {
        int x = (t >= o) ? sh[t - o] : 0;
        __syncthreads();
        sh[t] += x;
        __syncthreads();
    }
    int p = sh[t] - s;
#pragma unroll
    for (int i = 0; i < 4; i++) {
        if (base + i < TOTSEG) g_rowptr[base + i] = p;
        p += v[i];
    }
    if (t == 255) g_blksum[b] = sh[255];
}
__global__ void scan2_k() {
    if (threadIdx.x == 0) {
        int run = 0;
        for (int b = 0; b < NB_SCAN; b++) { g_blkoff[b] = run; run += g_blksum[b]; }
    }
}
__global__ void scan3_k() {
    int b = blockIdx.x, t = threadIdx.x;
    int off = g_blkoff[b];
    int base = b * 1024 + t * 4;
#pragma unroll
    for (int i = 0; i < 4; i++) {
        int idx = base + i;
        if (idx < TOTSEG) {
            int val = g_rowptr[idx] + off;
            g_rowptr[idx] = val;
            g_cursor[idx] = val;
        }
    }
    if (b == 0 && t == 0) g_rowptr[TOTSEG] = TOTE;
}
__global__ void scatter_k(const int* __restrict__ dst_idx) {
    int g = blockIdx.x * 256 + threadIdx.x;
    if (g >= TOTE) return;
    int r = g / E_;
    int pos = atomicAdd(&g_cursor[r * N_ + dst_idx[g]], 1);
    g_perm[pos] = g;
}

__global__ void agg_k(const int* __restrict__ src_idx,
                      const float* __restrict__ bias_g) {
    int gw = (blockIdx.x * 256 + threadIdx.x) >> 5;
    int lane = threadIdx.x & 31;
    if (gw >= TOTSEG) return;
    int r = gw / N_;
    int beg = g_rowptr[gw], end = g_rowptr[gw + 1];
    float4 er = g_er4[gw];
    const float4* elb = g_el4 + r * N_;

    float4 mx = make_float4(-INFINITY, -INFINITY, -INFINITY, -INFINITY);
    for (int i = beg + lane; i < end; i += 32) {
        int s = src_idx[g_perm[i]];
        float4 el = elb[s];
        mx.x = fmaxf(mx.x, lrelu(el.x + er.x));
        mx.y = fmaxf(mx.y, lrelu(el.y + er.y));
        mx.z = fmaxf(mx.z, lrelu(el.z + er.z));
        mx.w = fmaxf(mx.w, lrelu(el.w + er.w));
    }
#pragma unroll
    for (int o = 16; o; o >>= 1) {
        mx.x = fmaxf(mx.x, __shfl_xor_sync(0xffffffffu, mx.x, o));
        mx.y = fmaxf(mx.y, __shfl_xor_sync(0xffffffffu, mx.y, o));
        mx.z = fmaxf(mx.z, __shfl_xor_sync(0xffffffffu, mx.z, o));
        mx.w = fmaxf(mx.w, __shfl_xor_sync(0xffffffffu, mx.w, o));
    }

    const float* hsb = g_hs + (size_t)r * N_ * 128;
    float n0 = 0.f, n1 = 0.f, n2 = 0.f, n3 = 0.f;
    float s0 = 0.f, s1 = 0.f, s2 = 0.f, s3 = 0.f;
    for (int i = beg; i < end; i++) {
        int s = src_idx[g_perm[i]];
        float4 el = elb[s];
        float e0 = __expf(lrelu(el.x + er.x) - mx.x);
        float e1 = __expf(lrelu(el.y + er.y) - mx.y);
        float e2 = __expf(lrelu(el.z + er.z) - mx.z);
        float e3 = __expf(lrelu(el.w + er.w) - mx.w);
        s0 += e0; s1 += e1; s2 += e2; s3 += e3;
        const float* hr = hsb + (size_t)s * 128;
        n0 += e0 * hr[lane];
        n1 += e1 * hr[32 + lane];
        n2 += e2 * hr[64 + lane];
        n3 += e3 * hr[96 + lane];
    }
    const float* bg = bias_g + r * 128;
    float* zr = g_z + (size_t)gw * 128;
    zr[lane]      = elu1(n0 / (s0 + 1e-9f) + bg[lane]);
    zr[32 + lane] = elu1(n1 / (s1 + 1e-9f) + bg[32 + lane]);
    zr[64 + lane] = elu1(n2 / (s2 + 1e-9f) + bg[64 + lane]);
    zr[96 + lane] = elu1(n3 / (s3 + 1e-9f) + bg[96 + lane]);
}

__global__ void finish_a(float* __restrict__ out_att) {
    if (threadIdx.x == 0) {
        float w0 = g_wsum[0] / (float)N_;
        float w1 = g_wsum[1] / (float)N_;
        float w2 = g_wsum[2] / (float)N_;
        float m = fmaxf(w0, fmaxf(w1, w2));
        float e0 = __expf(w0 - m), e1 = __expf(w1 - m), e2 = __expf(w2 - m);
        float s = e0 + e1 + e2;
        g_a[0] = e0 / s; g_a[1] = e1 / s; g_a[2] = e2 / s;
        out_att[0] = g_a[0]; out_att[1] = g_a[1]; out_att[2] = g_a[2];
    }
}
__global__ void final_k(float* __restrict__ out) {
    int i = blockIdx.x * 256 + threadIdx.x;
    if (i >= N_ * 32) return;
    float a0 = g_a[0], a1 = g_a[1], a2 = g_a[2];
    const float4* z4 = (const float4*)g_z;
    float4 z0 = z4[i];
    float4 z1 = z4[(size_t)N_ * 32 + i];
    float4 z2 = z4[(size_t)2 * N_ * 32 + i];
    float4 o;
    o.x = a0 * z0.x + a1 * z1.x + a2 * z2.x;
    o.y = a0 * z0.y + a1 * z1.y + a2 * z2.y;
    o.z = a0 * z0.z + a1 * z1.z + a2 * z2.z;
    o.w = a0 * z0.w + a1 * z1.w + a2 * z2.w;
    ((float4*)out)[i] = o;
}

extern "C" void kernel_launch(void* const* d_in, const int* in_sizes, int n_in,
                              void* d_out, int out_size) {
    const float* dst_feat  = (const float*)d_in[0];
    const float* src_feats = (const float*)d_in[1];
    const int*   src_idx   = (const int*)d_in[2];
    const int*   dst_idx   = (const int*)d_in[3];
    const float* Wt_dst    = (const float*)d_in[4];
    const float* bt_src    = (const float*)d_in[7];
    const float* Wt_src    = (const float*)d_in[6];
    const float* bt_dst    = (const float*)d_in[5];
    const float* Wg        = (const float*)d_in[8];
    const float* attn_l    = (const float*)d_in[9];
    const float* attn_r    = (const float*)d_in[10];
    const float* bias_g    = (const float*)d_in[11];
    const float* W1        = (const float*)d_in[12];
    const float* b1        = (const float*)d_in[13];
    const float* W2        = (const float*)d_in[14];
    float* out = (float*)d_out;

    void *pWcs, *pWcd, *pbcs, *phs, *pz;
    cudaGetSymbolAddress(&pWcs, g_Wc_src);
    cudaGetSymbolAddress(&pWcd, g_Wc_dst);
    cudaGetSymbolAddress(&pbcs, g_bc_src);
    cudaGetSymbolAddress(&phs, g_hs);
    cudaGetSymbolAddress(&pz, g_z);

    // combined weights Wc = Wt @ Wg
    gemm_tile<0><<<dim3(1, 3), 256>>>(Wt_src, 128 * 128, 128, Wg, 128 * 128,
                                      nullptr, (float*)pWcs, 128 * 128, nullptr);
    gemm_tile<0><<<dim3(1, 3), 256>>>(Wt_dst, 0, 128, Wg, 128 * 128,
                                      nullptr, (float*)pWcd, 128 * 128, nullptr);
    prep_bias<<<2, 256>>>(bt_src, bt_dst, Wg);
    prep_uv<<<R_, 128>>>(attn_l, attn_r);

    // hs = src_feats @ Wc_src + bc_src
    gemm_tile<0><<<dim3((N_ + 127) / 128, 3), 256>>>(
        src_feats, (long long)N_ * 128, N_, (float*)pWcs, 128 * 128,
        (float*)pbcs, (float*)phs, (long long)N_ * 128, nullptr);

    attn_proj<<<(N_ + 7) / 8, 256>>>(src_feats, dst_feat);

    // CSR by destination
    zero_misc<<<(TOTSEG + 255) / 256, 256>>>();
    count_k<<<(TOTE + 255) / 256, 256>>>(dst_idx);
    scan1_k<<<NB_SCAN, 256>>>();
    scan2_k<<<1, 32>>>();
    scan3_k<<<NB_SCAN, 256>>>();
    scatter_k<<<(TOTE + 255) / 256, 256>>>(dst_idx);

    // GAT aggregation
    agg_k<<<(TOTSEG + 7) / 8, 256>>>(src_idx, bias_g);

    // semantic attention scalar sums: tanh(z@W1+b1)@W2, reduced
    gemm_tile<1><<<dim3((N_ + 127) / 128, 3), 256>>>(
        (float*)pz, (long long)N_ * 128, N_, W1, 0,
        b1, nullptr, 0, W2);

    finish_a<<<1, 32>>>(out + (size_t)N_ * 128);
    final_k<<<(N_ * 32 + 255) / 256, 256>>>(out);
}

// round 5
// speedup vs baseline: 1.4172x; 1.4172x over previous
#include <cuda_runtime.h>
#include <cuda_bf16.h>
#include <math.h>

#define N_ 100000
#define RPAD 100096
#define R_ 3
#define E_ 320000
#define TOTSEG (R_*N_)
#define TOTE (R_*E_)
#define NB_SCAN ((TOTSEG + 1023) / 1024)
#define WP 136
#define SMEM_MMA (2*128*WP*2 + 2*128*4)

// ----------------------------- device scratch ------------------------------
__device__ float g_Wc_src[R_*128*128];
__device__ float g_Wc_dst[R_*128*128];
__device__ float g_bc_src[R_*128];
__device__ float g_bc_dst[R_*128];
__device__ float g_V[R_*128*4];
__device__ float4 g_erb4[R_];
__device__ float g_hs[(size_t)R_*RPAD*128];
__device__ float4 g_el4[(size_t)R_*RPAD];
__device__ float4 g_er4[(size_t)R_*RPAD];
__device__ __nv_bfloat16 g_zhi[(size_t)R_*RPAD*128];
__device__ __nv_bfloat16 g_zlo[(size_t)R_*RPAD*128];
__device__ int   g_cnt[TOTSEG];
__device__ int   g_rowptr[TOTSEG + 1];
__device__ int   g_cursor[TOTSEG];
__device__ int   g_blksum[NB_SCAN];
__device__ int   g_blkoff[NB_SCAN];
__device__ int   g_perm[TOTE];
__device__ float g_wsum[R_];
__device__ float g_a[R_];

// ----------------------------- helpers -------------------------------------
__device__ __forceinline__ unsigned long long pk(float x, float y) {
    unsigned long long r;
    asm("mov.b64 %0, {%1, %2};" : "=l"(r) : "f"(x), "f"(y));
    return r;
}
__device__ __forceinline__ void fma2(unsigned long long& d, unsigned long long a,
                                     unsigned long long b) {
    asm("fma.rn.f32x2 %0, %1, %2, %0;" : "+l"(d) : "l"(a), "l"(b));
}
__device__ __forceinline__ float2 upk(unsigned long long v) {
    float2 f;
    asm("mov.b64 {%0, %1}, %2;" : "=f"(f.x), "=f"(f.y) : "l"(v));
    return f;
}
__device__ __forceinline__ float tanha(float x) {
    float y; asm("tanh.approx.f32 %0, %1;" : "=f"(y) : "f"(x)); return y;
}
__device__ __forceinline__ float lrelu(float x) { return x > 0.f ? x : 0.2f * x; }
__device__ __forceinline__ float elu1(float x)  { return x > 0.f ? x : (__expf(x) - 1.f); }

__device__ __forceinline__ void mma16816(float* c, const unsigned* a,
                                         unsigned b0, unsigned b1) {
    asm volatile(
        "mma.sync.aligned.m16n8k16.row.col.f32.bf16.bf16.f32 "
        "{%0,%1,%2,%3}, {%4,%5,%6,%7}, {%8,%9}, {%0,%1,%2,%3};"
        : "+f"(c[0]), "+f"(c[1]), "+f"(c[2]), "+f"(c[3])
        : "r"(a[0]), "r"(a[1]), "r"(a[2]), "r"(a[3]), "r"(b0), "r"(b1));
}

// --------------- tiny weight GEMMs: Wc = Wt @ Wg (6 tiles, one launch) -----
__global__ void __launch_bounds__(256) weights_k(const float* __restrict__ Wt_src,
                                                 const float* __restrict__ Wt_dst,
                                                 const float* __restrict__ Wg) {
    int y = blockIdx.x;
    int r = y % 3;
    const float* Ar = (y < 3) ? (Wt_src + r * 16384) : Wt_dst;
    const float* Wr = Wg + r * 16384;
    float* Cr = ((y < 3) ? g_Wc_src : g_Wc_dst) + r * 16384;

    __shared__ __align__(16) float sA[16][132];
    __shared__ __align__(16) float sB[16][128];
    int tid = threadIdx.x, tx = tid & 15, ty = tid >> 4;

    unsigned long long acc[8][4];
#pragma unroll
    for (int i = 0; i < 8; i++)
#pragma unroll
        for (int p = 0; p < 4; p++) acc[i][p] = 0ull;

    for (int kk = 0; kk < 128; kk += 16) {
#pragma unroll
        for (int l = 0; l < 2; l++) {
            int q = tid + l * 256;
            int row = q >> 2, ks = (q & 3) * 4;
            float4 v = *(const float4*)(Ar + (size_t)row * 128 + kk + ks);
            sA[ks + 0][row] = v.x; sA[ks + 1][row] = v.y;
            sA[ks + 2][row] = v.z; sA[ks + 3][row] = v.w;
        }
#pragma unroll
        for (int l = 0; l < 2; l++) {
            int q = tid + l * 256;
            int k = q >> 5, c = (q & 31) * 4;
            *(float4*)&sB[k][c] = *(const float4*)(Wr + (size_t)(kk + k) * 128 + c);
        }
        __syncthreads();
#pragma unroll
        for (int k = 0; k < 16; k++) {
            float4 a0 = *(const float4*)&sA[k][ty * 8];
            float4 a1 = *(const float4*)&sA[k][ty * 8 + 4];
            float4 b0 = *(const float4*)&sB[k][tx * 8];
            float4 b1 = *(const float4*)&sB[k][tx * 8 + 4];
            unsigned long long pb0 = pk(b0.x, b0.y), pb1 = pk(b0.z, b0.w);
            unsigned long long pb2 = pk(b1.x, b1.y), pb3 = pk(b1.z, b1.w);
            float av[8] = {a0.x, a0.y, a0.z, a0.w, a1.x, a1.y, a1.z, a1.w};
#pragma unroll
            for (int i = 0; i < 8; i++) {
                unsigned long long pa = pk(av[i], av[i]);
                fma2(acc[i][0], pa, pb0); fma2(acc[i][1], pa, pb1);
                fma2(acc[i][2], pa, pb2); fma2(acc[i][3], pa, pb3);
            }
        }
        __syncthreads();
    }
    int c0 = tx * 8;
#pragma unroll
    for (int i = 0; i < 8; i++) {
        int row = ty * 8 + i;
        float o[8];
#pragma unroll
        for (int p = 0; p < 4; p++) {
            float2 v = upk(acc[i][p]);
            o[2 * p] = v.x; o[2 * p + 1] = v.y;
        }
        *(float4*)(Cr + (size_t)row * 128 + c0) = make_float4(o[0], o[1], o[2], o[3]);
        *(float4*)(Cr + (size_t)row * 128 + c0 + 4) = make_float4(o[4], o[5], o[6], o[7]);
    }
}

// --------------- prep: combined biases (warp per output) -------------------
__global__ void prep_bias_k(const float* __restrict__ bt_src,
                            const float* __restrict__ bt_dst,
                            const float* __restrict__ Wg) {
    int gw = (blockIdx.x * blockDim.x + threadIdx.x) >> 5;
    int lane = threadIdx.x & 31;
    if (gw >= R_ * 128) return;
    int r = gw >> 7, c = gw & 127;
    float s1 = 0.f, s2 = 0.f;
#pragma unroll
    for (int i = 0; i < 4; i++) {
        int h = lane + i * 32;
        float w = Wg[r * 16384 + h * 128 + c];
        s1 += bt_src[r * 128 + h] * w;
        s2 += bt_dst[h] * w;
    }
#pragma unroll
    for (int o = 16; o; o >>= 1) {
        s1 += __shfl_xor_sync(0xffffffffu, s1, o);
        s2 += __shfl_xor_sync(0xffffffffu, s2, o);
    }
    if (lane == 0) { g_bc_src[gw] = s1; g_bc_dst[gw] = s2; }
}

// V[r][k][h] = sum_c Wc_dst[r][k][c]*ar[c] (head-blocked); warp per (r,k)
__global__ void prep_v_k(const float* __restrict__ attn_r) {
    int gw = (blockIdx.x * blockDim.x + threadIdx.x) >> 5;
    int lane = threadIdx.x & 31;
    if (gw >= R_ * 128) return;
    int r = gw >> 7, k = gw & 127;
    const float* Wcd = g_Wc_dst + r * 16384;
    const float* ar = attn_r + r * 128;
    float p[4];
#pragma unroll
    for (int h = 0; h < 4; h++)
        p[h] = Wcd[k * 128 + h * 32 + lane] * ar[h * 32 + lane];
#pragma unroll
    for (int o = 16; o; o >>= 1)
#pragma unroll
        for (int h = 0; h < 4; h++)
            p[h] += __shfl_xor_sync(0xffffffffu, p[h], o);
    if (lane == 0)
        *(float4*)&g_V[(r * 128 + k) * 4] = make_float4(p[0], p[1], p[2], p[3]);
}

__global__ void prep_erb_k(const float* __restrict__ attn_r) {
    int w = threadIdx.x >> 5, lane = threadIdx.x & 31;
    int r = w >> 2, h = w & 3;
    float v = g_bc_dst[r * 128 + h * 32 + lane] * attn_r[r * 128 + h * 32 + lane];
#pragma unroll
    for (int o = 16; o; o >>= 1) v += __shfl_xor_sync(0xffffffffu, v, o);
    if (lane == 0) ((float*)g_erb4)[r * 4 + h] = v;
}

// ----------------- bf16x3 tensor-core GEMM, A(rows x 128) @ W(128x128) -----
// MODE 0: A = fp32 (on-the-fly split), out = hs (+bias), epilogue also emits
//         el[row][head] = sum_col hs*attn_l.
// MODE 1: A = (Ahi,Alo) bf16, epilogue wsum[r] += sum tanh(C+b1)*W2 (valid rows)
template <int MODE>
__global__ void __launch_bounds__(256)
mma_gemm(const float* __restrict__ Afp,
         const __nv_bfloat16* __restrict__ Ahi,
         const __nv_bfloat16* __restrict__ Alo,
         const float* __restrict__ Wfp, int wstride,
         const float* __restrict__ bias, int bstride,
         const float* __restrict__ aux, int astride,
         float* __restrict__ Cout) {
    extern __shared__ char dsm[];
    __nv_bfloat16* sWhi = (__nv_bfloat16*)dsm;
    __nv_bfloat16* sWlo = sWhi + 128 * WP;
    float* sBias = (float*)(sWlo + 128 * WP);
    float* sAux  = sBias + 128;
    __shared__ float sred[8];

    int r = blockIdx.y;
    int tid = threadIdx.x;
    const float* Wr = Wfp + (size_t)r * wstride;
    for (int idx = tid; idx < 16384; idx += 256) {
        int k = idx >> 7, n = idx & 127;
        float w = Wr[idx];
        __nv_bfloat16 h = __float2bfloat16(w);
        sWhi[n * WP + k] = h;
        sWlo[n * WP + k] = __float2bfloat16(w - __bfloat162float(h));
    }
    if (tid < 128) {
        sBias[tid] = bias[r * bstride + tid];
        sAux[tid]  = aux[r * astride + tid];
    }
    __syncthreads();

    int lane = tid & 31, wid = tid >> 5;
    int warpM = wid >> 1, warpN = wid & 1;
    int g = lane >> 2, t = lane & 3;
    int row0 = blockIdx.x * 128;
    int rbase = row0 + warpM * 32;

    const float* af[4];
    const __nv_bfloat16 *php[4], *plp[4];
#pragma unroll
    for (int mt = 0; mt < 2; mt++)
#pragma unroll
        for (int hf = 0; hf < 2; hf++) {
            int row = rbase + mt * 16 + hf * 8 + g;
            int pi = mt * 2 + hf;
            if (MODE == 0) {
                int rc = row < N_ ? row : N_ - 1;
                af[pi] = Afp + (size_t)r * N_ * 128 + (size_t)rc * 128;
            } else {
                php[pi] = Ahi + ((size_t)r * RPAD + row) * 128;
                plp[pi] = Alo + ((size_t)r * RPAD + row) * 128;
            }
        }

    float c[2][8][4];
#pragma unroll
    for (int mt = 0; mt < 2; mt++)
#pragma unroll
        for (int nt = 0; nt < 8; nt++)
#pragma unroll
            for (int q = 0; q < 4; q++) c[mt][nt][q] = 0.f;

    for (int k0 = 0; k0 < 128; k0 += 16) {
        unsigned ah[2][4], al[2][4];
#pragma unroll
        for (int mt = 0; mt < 2; mt++)
#pragma unroll
            for (int jj = 0; jj < 4; jj++) {
                int pi = mt * 2 + (jj & 1);
                int ko = k0 + t * 2 + (jj >> 1) * 8;
                if (MODE == 0) {
                    float2 v = *(const float2*)(af[pi] + ko);
                    __nv_bfloat162 h2 = __floats2bfloat162_rn(v.x, v.y);
                    float lx = v.x - __low2float(h2);
                    float ly = v.y - __high2float(h2);
                    __nv_bfloat162 l2 = __floats2bfloat162_rn(lx, ly);
                    ah[mt][jj] = *(unsigned*)&h2;
                    al[mt][jj] = *(unsigned*)&l2;
                } else {
                    ah[mt][jj] = *(const unsigned*)(php[pi] + ko);
                    al[mt][jj] = *(const unsigned*)(plp[pi] + ko);
                }
            }
#pragma unroll
        for (int nt = 0; nt < 8; nt++) {
            int n = warpN * 64 + nt * 8 + g;
            const __nv_bfloat16* bp = &sWhi[n * WP + k0 + t * 2];
            unsigned bh0 = *(const unsigned*)bp;
            unsigned bh1 = *(const unsigned*)(bp + 8);
            const __nv_bfloat16* bq = &sWlo[n * WP + k0 + t * 2];
            unsigned bl0 = *(const unsigned*)bq;
            unsigned bl1 = *(const unsigned*)(bq + 8);
#pragma unroll
            for (int mt = 0; mt < 2; mt++) {
                mma16816(c[mt][nt], ah[mt], bh0, bh1);
                mma16816(c[mt][nt], ah[mt], bl0, bl1);
                mma16816(c[mt][nt], al[mt], bh0, bh1);
            }
        }
    }

    if (MODE == 0) {
        float* Cr = Cout + (size_t)r * RPAD * 128;
        float elp[2][2][2];
#pragma unroll
        for (int mt = 0; mt < 2; mt++)
#pragma unroll
            for (int hf = 0; hf < 2; hf++) { elp[mt][hf][0] = 0.f; elp[mt][hf][1] = 0.f; }
#pragma unroll
        for (int mt = 0; mt < 2; mt++)
#pragma unroll
            for (int nt = 0; nt < 8; nt++) {
                int n0 = warpN * 64 + nt * 8 + t * 2;
                float b0 = sBias[n0], b1v = sBias[n0 + 1];
                float a0 = sAux[n0],  a1 = sAux[n0 + 1];
                int rg = rbase + mt * 16 + g;
                float v00 = c[mt][nt][0] + b0, v01 = c[mt][nt][1] + b1v;
                float v10 = c[mt][nt][2] + b0, v11 = c[mt][nt][3] + b1v;
                *(float2*)&Cr[(size_t)rg * 128 + n0] = make_float2(v00, v01);
                *(float2*)&Cr[(size_t)(rg + 8) * 128 + n0] = make_float2(v10, v11);
                int hl = nt >> 2;
                elp[mt][0][hl] += v00 * a0 + v01 * a1;
                elp[mt][1][hl] += v10 * a0 + v11 * a1;
            }
#pragma unroll
        for (int mt = 0; mt < 2; mt++)
#pragma unroll
            for (int hf = 0; hf < 2; hf++)
#pragma unroll
                for (int hl = 0; hl < 2; hl++) {
                    float v = elp[mt][hf][hl];
                    v += __shfl_xor_sync(0xffffffffu, v, 1);
                    v += __shfl_xor_sync(0xffffffffu, v, 2);
                    elp[mt][hf][hl] = v;
                }
        if (t == 0) {
            float* elf = (float*)g_el4 + (size_t)r * RPAD * 4;
#pragma unroll
            for (int mt = 0; mt < 2; mt++)
#pragma unroll
                for (int hf = 0; hf < 2; hf++)
#pragma unroll
                    for (int hl = 0; hl < 2; hl++) {
                        int rg = rbase + mt * 16 + hf * 8 + g;
                        elf[(size_t)rg * 4 + warpN * 2 + hl] = elp[mt][hf][hl];
                    }
        }
    } else {
        float s = 0.f;
#pragma unroll
        for (int mt = 0; mt < 2; mt++)
#pragma unroll
            for (int nt = 0; nt < 8; nt++) {
                int n0 = warpN * 64 + nt * 8 + t * 2;
                float b0 = sBias[n0], b1v = sBias[n0 + 1];
                float w0 = sAux[n0],  w1 = sAux[n0 + 1];
                int rg = rbase + mt * 16 + g;
                if (rg < N_)
                    s += tanha(c[mt][nt][0] + b0) * w0 + tanha(c[mt][nt][1] + b1v) * w1;
                if (rg + 8 < N_)
                    s += tanha(c[mt][nt][2] + b0) * w0 + tanha(c[mt][nt][3] + b1v) * w1;
            }
#pragma unroll
        for (int o = 16; o; o >>= 1) s += __shfl_xor_sync(0xffffffffu, s, o);
        if (lane == 0) sred[wid] = s;
        __syncthreads();
        if (tid == 0) {
            float tt = 0.f;
#pragma unroll
            for (int j = 0; j < 8; j++) tt += sred[j];
            atomicAdd(&g_wsum[r], tt);
        }
    }
}

// ----------------- er per node (warp per node, dst only) -------------------
__global__ void attn_proj_er(const float* __restrict__ dst_feat) {
    int gw = (blockIdx.x * 256 + threadIdx.x) >> 5;
    int lane = threadIdx.x & 31;
    if (gw >= N_) return;
    float4 dv = *(const float4*)(dst_feat + (size_t)gw * 128 + lane * 4);
    float dvv[4] = {dv.x, dv.y, dv.z, dv.w};
#pragma unroll
    for (int r = 0; r < R_; r++) {
        const float4* V4 = (const float4*)(g_V + r * 512);
        float4 aD = make_float4(0, 0, 0, 0);
#pragma unroll
        for (int i = 0; i < 4; i++) {
            float4 w = V4[lane * 4 + i];
            aD.x += dvv[i] * w.x; aD.y += dvv[i] * w.y;
            aD.z += dvv[i] * w.z; aD.w += dvv[i] * w.w;
        }
#pragma unroll
        for (int o = 16; o; o >>= 1) {
            aD.x += __shfl_xor_sync(0xffffffffu, aD.x, o);
            aD.y += __shfl_xor_sync(0xffffffffu, aD.y, o);
            aD.z += __shfl_xor_sync(0xffffffffu, aD.z, o);
            aD.w += __shfl_xor_sync(0xffffffffu, aD.w, o);
        }
        if (lane == 0) {
            float4 rb = g_erb4[r];
            g_er4[(size_t)r * RPAD + gw] =
                make_float4(aD.x + rb.x, aD.y + rb.y, aD.z + rb.z, aD.w + rb.w);
        }
    }
}

// ----------------------------- CSR build -----------------------------------
__global__ void zero_misc() {
    int t = blockIdx.x * 256 + threadIdx.x;
    if (t < TOTSEG) g_cnt[t] = 0;
    if (t < R_) g_wsum[t] = 0.f;
}
__global__ void count_k(const int* __restrict__ dst_idx) {
    int g = blockIdx.x * 256 + threadIdx.x;
    if (g >= TOTE) return;
    int r = g / E_;
    atomicAdd(&g_cnt[r * N_ + dst_idx[g]], 1);
}
__global__ void scan1_k() {
    __shared__ int sh[256];
    int b = blockIdx.x, t = threadIdx.x;
    int base = b * 1024 + t * 4;
    int v[4];
#pragma unroll
    for (int i = 0; i < 4; i++) v[i] = (base + i < TOTSEG) ? g_cnt[base + i] : 0;
    int s = v[0] + v[1] + v[2] + v[3];
    sh[t] = s;
    __syncthreads();
    for (int o = 1; o < 256; o <<= 1) {
        int x = (t >= o) ? sh[t - o] : 0;
        __syncthreads();
        sh[t] += x;
        __syncthreads();
    }
    int p = sh[t] - s;
#pragma unroll
    for (int i = 0; i < 4; i++) {
        if (base + i < TOTSEG) g_rowptr[base + i] = p;
        p += v[i];
    }
    if (t == 255) g_blksum[b] = sh[255];
}
__global__ void scan2_k() {
    if (threadIdx.x == 0) {
        int run = 0;
        for (int b = 0; b < NB_SCAN; b++) { g_blkoff[b] = run; run += g_blksum[b]; }
    }
}
__global__ void scan3_k() {
    int b = blockIdx.x, t = threadIdx.x;
    int off = g_blkoff[b];
    int base = b * 1024 + t * 4;
#pragma unroll
    for (int i = 0; i < 4; i++) {
        int idx = base + i;
        if (idx < TOTSEG) {
            int val = g_rowptr[idx] + off;
            g_rowptr[idx] = val;
            g_cursor[idx] = val;
        }
    }
    if (b == 0 && t == 0) g_rowptr[TOTSEG] = TOTE;
}
__global__ void scatter_k(const int* __restrict__ dst_idx) {
    int g = blockIdx.x * 256 + threadIdx.x;
    if (g >= TOTE) return;
    int r = g / E_;
    int pos = atomicAdd(&g_cursor[r * N_ + dst_idx[g]], 1);
    g_perm[pos] = g;
}

// -------------------- GAT aggregation (warp per node x rel) ----------------
__global__ void agg_k(const int* __restrict__ src_idx,
                      const float* __restrict__ bias_g) {
    int gw = (blockIdx.x * 256 + threadIdx.x) >> 5;
    int lane = threadIdx.x & 31;
    if (gw >= TOTSEG) return;
    int r = gw / N_;
    int n = gw - r * N_;
    int beg = g_rowptr[gw], end = g_rowptr[gw + 1];
    float4 er = g_er4[(size_t)r * RPAD + n];
    const float4* elb = g_el4 + (size_t)r * RPAD;

    float4 mx = make_float4(-INFINITY, -INFINITY, -INFINITY, -INFINITY);
    for (int i = beg + lane; i < end; i += 32) {
        int s = src_idx[g_perm[i]];
        float4 el = elb[s];
        mx.x = fmaxf(mx.x, lrelu(el.x + er.x));
        mx.y = fmaxf(mx.y, lrelu(el.y + er.y));
        mx.z = fmaxf(mx.z, lrelu(el.z + er.z));
        mx.w = fmaxf(mx.w, lrelu(el.w + er.w));
    }
#pragma unroll
    for (int o = 16; o; o >>= 1) {
        mx.x = fmaxf(mx.x, __shfl_xor_sync(0xffffffffu, mx.x, o));
        mx.y = fmaxf(mx.y, __shfl_xor_sync(0xffffffffu, mx.y, o));
        mx.z = fmaxf(mx.z, __shfl_xor_sync(0xffffffffu, mx.z, o));
        mx.w = fmaxf(mx.w, __shfl_xor_sync(0xffffffffu, mx.w, o));
    }

    const float* hsb = g_hs + (size_t)r * RPAD * 128;
    float n0 = 0.f, n1 = 0.f, n2 = 0.f, n3 = 0.f;
    float s0 = 0.f, s1 = 0.f, s2 = 0.f, s3 = 0.f;
    for (int i = beg; i < end; i++) {
        int s = src_idx[g_perm[i]];
        float4 el = elb[s];
        float e0 = __expf(lrelu(el.x + er.x) - mx.x);
        float e1 = __expf(lrelu(el.y + er.y) - mx.y);
        float e2 = __expf(lrelu(el.z + er.z) - mx.z);
        float e3 = __expf(lrelu(el.w + er.w) - mx.w);
        s0 += e0; s1 += e1; s2 += e2; s3 += e3;
        const float* hr = hsb + (size_t)s * 128;
        n0 += e0 * hr[lane];
        n1 += e1 * hr[32 + lane];
        n2 += e2 * hr[64 + lane];
        n3 += e3 * hr[96 + lane];
    }
    const float* bg = bias_g + r * 128;
    size_t zo = ((size_t)r * RPAD + n) * 128;
    float z; __nv_bfloat16 h;
    z = elu1(n0 / (s0 + 1e-9f) + bg[lane]);
    h = __float2bfloat16(z);
    g_zhi[zo + lane] = h; g_zlo[zo + lane] = __float2bfloat16(z - __bfloat162float(h));
    z = elu1(n1 / (s1 + 1e-9f) + bg[32 + lane]);
    h = __float2bfloat16(z);
    g_zhi[zo + 32 + lane] = h; g_zlo[zo + 32 + lane] = __float2bfloat16(z - __bfloat162float(h));
    z = elu1(n2 / (s2 + 1e-9f) + bg[64 + lane]);
    h = __float2bfloat16(z);
    g_zhi[zo + 64 + lane] = h; g_zlo[zo + 64 + lane] = __float2bfloat16(z - __bfloat162float(h));
    z = elu1(n3 / (s3 + 1e-9f) + bg[96 + lane]);
    h = __float2bfloat16(z);
    g_zhi[zo + 96 + lane] = h; g_zlo[zo + 96 + lane] = __float2bfloat16(z - __bfloat162float(h));
}

// -------------------- semantic softmax + combine ---------------------------
__global__ void finish_a(float* __restrict__ out_att) {
    if (threadIdx.x == 0) {
        float w0 = g_wsum[0] / (float)N_;
        float w1 = g_wsum[1] / (float)N_;
        float w2 = g_wsum[2] / (float)N_;
        float m = fmaxf(w0, fmaxf(w1, w2));
        float e0 = __expf(w0 - m), e1 = __expf(w1 - m), e2 = __expf(w2 - m);
        float s = e0 + e1 + e2;
        g_a[0] = e0 / s; g_a[1] = e1 / s; g_a[2] = e2 / s;
        out_att[0] = g_a[0]; out_att[1] = g_a[1]; out_att[2] = g_a[2];
    }
}
__global__ void final_k(float* __restrict__ out) {
    size_t i = (size_t)blockIdx.x * 256 + threadIdx.x;
    if (i >= (size_t)N_ * 32) return;
    size_t e = i * 4;
    float av[3] = {g_a[0], g_a[1], g_a[2]};
    float o[4] = {0.f, 0.f, 0.f, 0.f};
#pragma unroll
    for (int r = 0; r < R_; r++) {
        uint2 hh = *(const uint2*)(g_zhi + (size_t)r * RPAD * 128 + e);
        uint2 ll = *(const uint2*)(g_zlo + (size_t)r * RPAD * 128 + e);
        __nv_bfloat162 h0 = *(__nv_bfloat162*)&hh.x, h1 = *(__nv_bfloat162*)&hh.y;
        __nv_bfloat162 l0 = *(__nv_bfloat162*)&ll.x, l1 = *(__nv_bfloat162*)&ll.y;
        float a = av[r];
        o[0] += a * (__low2float(h0) + __low2float(l0));
        o[1] += a * (__high2float(h0) + __high2float(l0));
        o[2] += a * (__low2float(h1) + __low2float(l1));
        o[3] += a * (__high2float(h1) + __high2float(l1));
    }
    *(float4*)(out + e) = make_float4(o[0], o[1], o[2], o[3]);
}

// ----------------------------- launcher ------------------------------------
extern "C" void kernel_launch(void* const* d_in, const int* in_sizes, int n_in,
                              void* d_out, int out_size) {
    const float* dst_feat  = (const float*)d_in[0];
    const float* src_feats = (const float*)d_in[1];
    const int*   src_idx   = (const int*)d_in[2];
    const int*   dst_idx   = (const int*)d_in[3];
    const float* Wt_dst    = (const float*)d_in[4];
    const float* bt_dst    = (const float*)d_in[5];
    const float* Wt_src    = (const float*)d_in[6];
    const float* bt_src    = (const float*)d_in[7];
    const float* Wg        = (const float*)d_in[8];
    const float* attn_l    = (const float*)d_in[9];
    const float* attn_r    = (const float*)d_in[10];
    const float* bias_g    = (const float*)d_in[11];
    const float* W1        = (const float*)d_in[12];
    const float* b1        = (const float*)d_in[13];
    const float* W2        = (const float*)d_in[14];
    float* out = (float*)d_out;

    void *pWcs, *pbcs, *phs, *pzhi, *pzlo;
    cudaGetSymbolAddress(&pWcs, g_Wc_src);
    cudaGetSymbolAddress(&pbcs, g_bc_src);
    cudaGetSymbolAddress(&phs, g_hs);
    cudaGetSymbolAddress(&pzhi, g_zhi);
    cudaGetSymbolAddress(&pzlo, g_zlo);

    cudaFuncSetAttribute(mma_gemm<0>, cudaFuncAttributeMaxDynamicSharedMemorySize, SMEM_MMA);
    cudaFuncSetAttribute(mma_gemm<1>, cudaFuncAttributeMaxDynamicSharedMemorySize, SMEM_MMA);

    prep_bias_k<<<48, 256>>>(bt_src, bt_dst, Wg);
    weights_k<<<6, 256>>>(Wt_src, Wt_dst, Wg);
    prep_v_k<<<48, 256>>>(attn_r);
    prep_erb_k<<<1, 384>>>(attn_r);

    zero_misc<<<(TOTSEG + 255) / 256, 256>>>();
    count_k<<<(TOTE + 255) / 256, 256>>>(dst_idx);
    scan1_k<<<NB_SCAN, 256>>>();
    scan2_k<<<1, 32>>>();
    scan3_k<<<NB_SCAN, 256>>>();
    scatter_k<<<(TOTE + 255) / 256, 256>>>(dst_idx);

    // hs = src @ Wc_src + bc  (bf16x3 tensor cores) + fused el epilogue
    mma_gemm<0><<<dim3(RPAD / 128, 3), 256, SMEM_MMA>>>(
        src_feats, nullptr, nullptr, (const float*)pWcs, 16384,
        (const float*)pbcs, 128, attn_l, 128, (float*)phs);

    attn_proj_er<<<(N_ + 7) / 8, 256>>>(dst_feat);

    agg_k<<<(TOTSEG + 7) / 8, 256>>>(src_idx, bias_g);

    // wsum[r] = sum_n tanh(z@W1+b1)@W2  (bf16x3 tensor cores, fused reduce)
    mma_gemm<1><<<dim3(RPAD / 128, 3), 256, SMEM_MMA>>>(
        nullptr, (const __nv_bfloat16*)pzhi, (const __nv_bfloat16*)pzlo,
        W1, 0, b1, 0, W2, 0, nullptr);

    finish_a<<<1, 32>>>(out + (size_t)N_ * 128);
    final_k<<<(N_ * 32 + 255) / 256, 256>>>(out);
}

// round 6
// speedup vs baseline: 1.5468x; 1.0915x over previous
#include <cuda_runtime.h>
#include <cuda_bf16.h>
#include <math.h>

#define N_ 100000
#define RPAD 100096
#define R_ 3
#define E_ 320000
#define TOTSEG (R_*N_)
#define TOTE (R_*E_)
#define NB_SCAN ((TOTSEG + 1023) / 1024)
#define NB_ZERO ((TOTSEG + 255) / 256)
#define WP 136
#define SMEM_MMA (2*128*WP*2 + 2*128*4)

// ----------------------------- device scratch ------------------------------
__device__ float g_Wc_src[R_*128*128];
__device__ float g_Wc_dst[R_*128*128];
__device__ float g_bc_src[R_*128];
__device__ float g_bc_dst[R_*128];
__device__ float g_V[R_*128*4];
__device__ float4 g_erb4[R_];
__device__ float g_hs[(size_t)R_*RPAD*128];
__device__ float g_z[(size_t)R_*RPAD*128];
__device__ float4 g_el4[(size_t)R_*RPAD];
__device__ float4 g_er4[(size_t)R_*RPAD];
__device__ int   g_cnt[TOTSEG];
__device__ int   g_rowptr[TOTSEG + 1];
__device__ int   g_cursor[TOTSEG];
__device__ int   g_blksum[NB_SCAN];
__device__ int   g_blkoff[NB_SCAN];
__device__ int   g_srcsorted[TOTE];
__device__ float g_wsum[R_];

// ----------------------------- helpers -------------------------------------
__device__ __forceinline__ unsigned long long pk(float x, float y) {
    unsigned long long r;
    asm("mov.b64 %0, {%1, %2};" : "=l"(r) : "f"(x), "f"(y));
    return r;
}
__device__ __forceinline__ void fma2(unsigned long long& d, unsigned long long a,
                                     unsigned long long b) {
    asm("fma.rn.f32x2 %0, %1, %2, %0;" : "+l"(d) : "l"(a), "l"(b));
}
__device__ __forceinline__ float2 upk(unsigned long long v) {
    float2 f;
    asm("mov.b64 {%0, %1}, %2;" : "=f"(f.x), "=f"(f.y) : "l"(v));
    return f;
}
__device__ __forceinline__ float tanha(float x) {
    float y; asm("tanh.approx.f32 %0, %1;" : "=f"(y) : "f"(x)); return y;
}
__device__ __forceinline__ float lrelu(float x) { return x > 0.f ? x : 0.2f * x; }
__device__ __forceinline__ float elu1(float x)  { return x > 0.f ? x : (__expf(x) - 1.f); }

__device__ __forceinline__ void mma16816(float* c, const unsigned* a,
                                         unsigned b0, unsigned b1) {
    asm volatile(
        "mma.sync.aligned.m16n8k16.row.col.f32.bf16.bf16.f32 "
        "{%0,%1,%2,%3}, {%4,%5,%6,%7}, {%8,%9}, {%0,%1,%2,%3};"
        : "+f"(c[0]), "+f"(c[1]), "+f"(c[2]), "+f"(c[3])
        : "r"(a[0]), "r"(a[1]), "r"(a[2]), "r"(a[3]), "r"(b0), "r"(b1));
}

// ---------------- P1: zero + weight GEMMs + combined biases ----------------
__global__ void __launch_bounds__(256) p1_k(const float* __restrict__ Wt_src,
                                            const float* __restrict__ Wt_dst,
                                            const float* __restrict__ Wg,
                                            const float* __restrict__ bt_src,
                                            const float* __restrict__ bt_dst) {
    int b = blockIdx.x;
    int tid = threadIdx.x;
    if (b >= 54) {                      // zero section
        int t = (b - 54) * 256 + tid;
        if (t < TOTSEG) g_cnt[t] = 0;
        if (t < R_) g_wsum[t] = 0.f;
        return;
    }
    if (b >= 6) {                       // combined biases: warp per output
        int gw = (b - 6) * 8 + (tid >> 5);
        int lane = tid & 31;
        if (gw >= R_ * 128) return;
        int r = gw >> 7, c = gw & 127;
        float s1 = 0.f, s2 = 0.f;
#pragma unroll
        for (int i = 0; i < 4; i++) {
            int h = lane + i * 32;
            float w = Wg[r * 16384 + h * 128 + c];
            s1 += bt_src[r * 128 + h] * w;
            s2 += bt_dst[h] * w;
        }
#pragma unroll
        for (int o = 16; o; o >>= 1) {
            s1 += __shfl_xor_sync(0xffffffffu, s1, o);
            s2 += __shfl_xor_sync(0xffffffffu, s2, o);
        }
        if (lane == 0) { g_bc_src[gw] = s1; g_bc_dst[gw] = s2; }
        return;
    }
    // weight GEMM tile: Wc = Wt @ Wg
    int r = b % 3;
    const float* Ar = (b < 3) ? (Wt_src + r * 16384) : Wt_dst;
    const float* Wr = Wg + r * 16384;
    float* Cr = ((b < 3) ? g_Wc_src : g_Wc_dst) + r * 16384;

    __shared__ __align__(16) float sA[16][132];
    __shared__ __align__(16) float sB[16][128];
    int tx = tid & 15, ty = tid >> 4;

    unsigned long long acc[8][4];
#pragma unroll
    for (int i = 0; i < 8; i++)
#pragma unroll
        for (int p = 0; p < 4; p++) acc[i][p] = 0ull;

    for (int kk = 0; kk < 128; kk += 16) {
#pragma unroll
        for (int l = 0; l < 2; l++) {
            int q = tid + l * 256;
            int row = q >> 2, ks = (q & 3) * 4;
            float4 v = *(const float4*)(Ar + (size_t)row * 128 + kk + ks);
            sA[ks + 0][row] = v.x; sA[ks + 1][row] = v.y;
            sA[ks + 2][row] = v.z; sA[ks + 3][row] = v.w;
        }
#pragma unroll
        for (int l = 0; l < 2; l++) {
            int q = tid + l * 256;
            int k = q >> 5, c = (q & 31) * 4;
            *(float4*)&sB[k][c] = *(const float4*)(Wr + (size_t)(kk + k) * 128 + c);
        }
        __syncthreads();
#pragma unroll
        for (int k = 0; k < 16; k++) {
            float4 a0 = *(const float4*)&sA[k][ty * 8];
            float4 a1 = *(const float4*)&sA[k][ty * 8 + 4];
            float4 b0 = *(const float4*)&sB[k][tx * 8];
            float4 b1v = *(const float4*)&sB[k][tx * 8 + 4];
            unsigned long long pb0 = pk(b0.x, b0.y), pb1 = pk(b0.z, b0.w);
            unsigned long long pb2 = pk(b1v.x, b1v.y), pb3 = pk(b1v.z, b1v.w);
            float av[8] = {a0.x, a0.y, a0.z, a0.w, a1.x, a1.y, a1.z, a1.w};
#pragma unroll
            for (int i = 0; i < 8; i++) {
                unsigned long long pa = pk(av[i], av[i]);
                fma2(acc[i][0], pa, pb0); fma2(acc[i][1], pa, pb1);
                fma2(acc[i][2], pa, pb2); fma2(acc[i][3], pa, pb3);
            }
        }
        __syncthreads();
    }
    int c0 = tx * 8;
#pragma unroll
    for (int i = 0; i < 8; i++) {
        int row = ty * 8 + i;
        float o[8];
#pragma unroll
        for (int p = 0; p < 4; p++) {
            float2 v = upk(acc[i][p]);
            o[2 * p] = v.x; o[2 * p + 1] = v.y;
        }
        *(float4*)(Cr + (size_t)row * 128 + c0) = make_float4(o[0], o[1], o[2], o[3]);
        *(float4*)(Cr + (size_t)row * 128 + c0 + 4) = make_float4(o[4], o[5], o[6], o[7]);
    }
}

// ---------------- P2: V projection + er bias -------------------------------
__global__ void __launch_bounds__(256) p2_k(const float* __restrict__ attn_r) {
    int b = blockIdx.x;
    int tid = threadIdx.x;
    int lane = tid & 31;
    if (b == 48) {                      // erb: 12 warps
        int w = tid >> 5;
        if (w >= 12) return;
        int r = w >> 2, h = w & 3;
        float v = g_bc_dst[r * 128 + h * 32 + lane] * attn_r[r * 128 + h * 32 + lane];
#pragma unroll
        for (int o = 16; o; o >>= 1) v += __shfl_xor_sync(0xffffffffu, v, o);
        if (lane == 0) ((float*)g_erb4)[r * 4 + h] = v;
        return;
    }
    int gw = b * 8 + (tid >> 5);
    if (gw >= R_ * 128) return;
    int r = gw >> 7, k = gw & 127;
    const float* Wcd = g_Wc_dst + r * 16384;
    const float* ar = attn_r + r * 128;
    float p[4];
#pragma unroll
    for (int h = 0; h < 4; h++)
        p[h] = Wcd[k * 128 + h * 32 + lane] * ar[h * 32 + lane];
#pragma unroll
    for (int o = 16; o; o >>= 1)
#pragma unroll
        for (int h = 0; h < 4; h++)
            p[h] += __shfl_xor_sync(0xffffffffu, p[h], o);
    if (lane == 0)
        *(float4*)&g_V[(r * 128 + k) * 4] = make_float4(p[0], p[1], p[2], p[3]);
}

// ----------------- bf16x3 tensor-core GEMM, A(rows x 128) @ W(128x128) -----
// A is fp32, split on the fly. MODE 0: store hs (+bias) + fused el epilogue.
// MODE 1: wsum[r] += sum_{valid rows} tanh(C + b1) * W2
template <int MODE>
__global__ void __launch_bounds__(256)
mma_gemm(const float* __restrict__ Afp, int arows, long long alead,
         const float* __restrict__ Wfp, int wstride,
         const float* __restrict__ bias, int bstride,
         const float* __restrict__ aux, int astride,
         float* __restrict__ Cout) {
    extern __shared__ char dsm[];
    __nv_bfloat16* sWhi = (__nv_bfloat16*)dsm;
    __nv_bfloat16* sWlo = sWhi + 128 * WP;
    float* sBias = (float*)(sWlo + 128 * WP);
    float* sAux  = sBias + 128;
    __shared__ float sred[8];

    int r = blockIdx.y;
    int tid = threadIdx.x;
    const float* Wr = Wfp + (size_t)r * wstride;
    for (int idx = tid; idx < 16384; idx += 256) {
        int k = idx >> 7, n = idx & 127;
        float w = Wr[idx];
        __nv_bfloat16 h = __float2bfloat16(w);
        sWhi[n * WP + k] = h;
        sWlo[n * WP + k] = __float2bfloat16(w - __bfloat162float(h));
    }
    if (tid < 128) {
        sBias[tid] = bias[r * bstride + tid];
        sAux[tid]  = aux[r * astride + tid];
    }
    __syncthreads();

    int lane = tid & 31, wid = tid >> 5;
    int warpM = wid >> 1, warpN = wid & 1;
    int g = lane >> 2, t = lane & 3;
    int row0 = blockIdx.x * 128;
    int rbase = row0 + warpM * 32;

    const float* af[4];
#pragma unroll
    for (int mt = 0; mt < 2; mt++)
#pragma unroll
        for (int hf = 0; hf < 2; hf++) {
            int row = rbase + mt * 16 + hf * 8 + g;
            int rc = (MODE == 0) ? (row < arows ? row : arows - 1) : row;
            af[mt * 2 + hf] = Afp + (size_t)r * alead + (size_t)rc * 128;
        }

    float c[2][8][4];
#pragma unroll
    for (int mt = 0; mt < 2; mt++)
#pragma unroll
        for (int nt = 0; nt < 8; nt++)
#pragma unroll
            for (int q = 0; q < 4; q++) c[mt][nt][q] = 0.f;

    for (int k0 = 0; k0 < 128; k0 += 16) {
        unsigned ah[2][4], al[2][4];
#pragma unroll
        for (int mt = 0; mt < 2; mt++)
#pragma unroll
            for (int jj = 0; jj < 4; jj++) {
                int pi = mt * 2 + (jj & 1);
                int ko = k0 + t * 2 + (jj >> 1) * 8;
                float2 v = *(const float2*)(af[pi] + ko);
                __nv_bfloat162 h2 = __floats2bfloat162_rn(v.x, v.y);
                float lx = v.x - __low2float(h2);
                float ly = v.y - __high2float(h2);
                __nv_bfloat162 l2 = __floats2bfloat162_rn(lx, ly);
                ah[mt][jj] = *(unsigned*)&h2;
                al[mt][jj] = *(unsigned*)&l2;
            }
#pragma unroll
        for (int nt = 0; nt < 8; nt++) {
            int n = warpN * 64 + nt * 8 + g;
            const __nv_bfloat16* bp = &sWhi[n * WP + k0 + t * 2];
            unsigned bh0 = *(const unsigned*)bp;
            unsigned bh1 = *(const unsigned*)(bp + 8);
            const __nv_bfloat16* bq = &sWlo[n * WP + k0 + t * 2];
            unsigned bl0 = *(const unsigned*)bq;
            unsigned bl1 = *(const unsigned*)(bq + 8);
#pragma unroll
            for (int mt = 0; mt < 2; mt++) {
                mma16816(c[mt][nt], ah[mt], bh0, bh1);
                mma16816(c[mt][nt], ah[mt], bl0, bl1);
                mma16816(c[mt][nt], al[mt], bh0, bh1);
            }
        }
    }

    if (MODE == 0) {
        float* Cr = Cout + (size_t)r * RPAD * 128;
        float elp[2][2][2];
#pragma unroll
        for (int mt = 0; mt < 2; mt++)
#pragma unroll
            for (int hf = 0; hf < 2; hf++) { elp[mt][hf][0] = 0.f; elp[mt][hf][1] = 0.f; }
#pragma unroll
        for (int mt = 0; mt < 2; mt++)
#pragma unroll
            for (int nt = 0; nt < 8; nt++) {
                int n0 = warpN * 64 + nt * 8 + t * 2;
                float b0 = sBias[n0], b1v = sBias[n0 + 1];
                float a0 = sAux[n0],  a1 = sAux[n0 + 1];
                int rg = rbase + mt * 16 + g;
                float v00 = c[mt][nt][0] + b0, v01 = c[mt][nt][1] + b1v;
                float v10 = c[mt][nt][2] + b0, v11 = c[mt][nt][3] + b1v;
                *(float2*)&Cr[(size_t)rg * 128 + n0] = make_float2(v00, v01);
                *(float2*)&Cr[(size_t)(rg + 8) * 128 + n0] = make_float2(v10, v11);
                int hl = nt >> 2;
                elp[mt][0][hl] += v00 * a0 + v01 * a1;
                elp[mt][1][hl] += v10 * a0 + v11 * a1;
            }
#pragma unroll
        for (int mt = 0; mt < 2; mt++)
#pragma unroll
            for (int hf = 0; hf < 2; hf++)
#pragma unroll
                for (int hl = 0; hl < 2; hl++) {
                    float v = elp[mt][hf][hl];
                    v += __shfl_xor_sync(0xffffffffu, v, 1);
                    v += __shfl_xor_sync(0xffffffffu, v, 2);
                    elp[mt][hf][hl] = v;
                }
        if (t == 0) {
            float* elf = (float*)g_el4 + (size_t)r * RPAD * 4;
#pragma unroll
            for (int mt = 0; mt < 2; mt++)
#pragma unroll
                for (int hf = 0; hf < 2; hf++)
#pragma unroll
                    for (int hl = 0; hl < 2; hl++) {
                        int rg = rbase + mt * 16 + hf * 8 + g;
                        elf[(size_t)rg * 4 + warpN * 2 + hl] = elp[mt][hf][hl];
                    }
        }
    } else {
        float s = 0.f;
#pragma unroll
        for (int mt = 0; mt < 2; mt++)
#pragma unroll
            for (int nt = 0; nt < 8; nt++) {
                int n0 = warpN * 64 + nt * 8 + t * 2;
                float b0 = sBias[n0], b1v = sBias[n0 + 1];
                float w0 = sAux[n0],  w1 = sAux[n0 + 1];
                int rg = rbase + mt * 16 + g;
                if (rg < N_)
                    s += tanha(c[mt][nt][0] + b0) * w0 + tanha(c[mt][nt][1] + b1v) * w1;
                if (rg + 8 < N_)
                    s += tanha(c[mt][nt][2] + b0) * w0 + tanha(c[mt][nt][3] + b1v) * w1;
            }
#pragma unroll
        for (int o = 16; o; o >>= 1) s += __shfl_xor_sync(0xffffffffu, s, o);
        if (lane == 0) sred[wid] = s;
        __syncthreads();
        if (tid == 0) {
            float tt = 0.f;
#pragma unroll
            for (int j = 0; j < 8; j++) tt += sred[j];
            atomicAdd(&g_wsum[r], tt);
        }
    }
}

// ----------------- er per node (warp per node) -----------------------------
__global__ void attn_proj_er(const float* __restrict__ dst_feat) {
    int gw = (blockIdx.x * 256 + threadIdx.x) >> 5;
    int lane = threadIdx.x & 31;
    if (gw >= N_) return;
    float4 dv = *(const float4*)(dst_feat + (size_t)gw * 128 + lane * 4);
    float dvv[4] = {dv.x, dv.y, dv.z, dv.w};
#pragma unroll
    for (int r = 0; r < R_; r++) {
        const float4* V4 = (const float4*)(g_V + r * 512);
        float4 aD = make_float4(0, 0, 0, 0);
#pragma unroll
        for (int i = 0; i < 4; i++) {
            float4 w = V4[lane * 4 + i];
            aD.x += dvv[i] * w.x; aD.y += dvv[i] * w.y;
            aD.z += dvv[i] * w.z; aD.w += dvv[i] * w.w;
        }
#pragma unroll
        for (int o = 16; o; o >>= 1) {
            aD.x += __shfl_xor_sync(0xffffffffu, aD.x, o);
            aD.y += __shfl_xor_sync(0xffffffffu, aD.y, o);
            aD.z += __shfl_xor_sync(0xffffffffu, aD.z, o);
            aD.w += __shfl_xor_sync(0xffffffffu, aD.w, o);
        }
        if (lane == 0) {
            float4 rb = g_erb4[r];
            g_er4[(size_t)r * RPAD + gw] =
                make_float4(aD.x + rb.x, aD.y + rb.y, aD.z + rb.z, aD.w + rb.w);
        }
    }
}

// ----------------------------- CSR build -----------------------------------
__global__ void count_k(const int* __restrict__ dst_idx) {
    int g = blockIdx.x * 256 + threadIdx.x;
    if (g >= TOTE) return;
    int r = g / E_;
    atomicAdd(&g_cnt[r * N_ + dst_idx[g]], 1);
}
__global__ void scan1_k() {
    __shared__ int sh[256];
    int b = blockIdx.x, t = threadIdx.x;
    int base = b * 1024 + t * 4;
    int v[4];
#pragma unroll
    for (int i = 0; i < 4; i++) v[i] = (base + i < TOTSEG) ? g_cnt[base + i] : 0;
    int s = v[0] + v[1] + v[2] + v[3];
    sh[t] = s;
    __syncthreads();
    for (int o = 1; o < 256; o <<= 1) {
        int x = (t >= o) ? sh[t - o] : 0;
        __syncthreads();
        sh[t] += x;
        __syncthreads();
    }
    int p = sh[t] - s;
#pragma unroll
    for (int i = 0; i < 4; i++) {
        if (base + i < TOTSEG) g_rowptr[base + i] = p;
        p += v[i];
    }
    if (t == 255) g_blksum[b] = sh[255];
}
__global__ void scan2_k() {
    if (threadIdx.x == 0) {
        int run = 0;
        for (int b = 0; b < NB_SCAN; b++) { g_blkoff[b] = run; run += g_blksum[b]; }
    }
}
__global__ void scan3_k() {
    int b = blockIdx.x, t = threadIdx.x;
    int off = g_blkoff[b];
    int base = b * 1024 + t * 4;
#pragma unroll
    for (int i = 0; i < 4; i++) {
        int idx = base + i;
        if (idx < TOTSEG) {
            int val = g_rowptr[idx] + off;
            g_rowptr[idx] = val;
            g_cursor[idx] = val;
        }
    }
    if (b == 0 && t == 0) g_rowptr[TOTSEG] = TOTE;
}
// store SRC node id directly at sorted position (kills one indirection in agg)
__global__ void scatter_k(const int* __restrict__ dst_idx,
                          const int* __restrict__ src_idx) {
    int g = blockIdx.x * 256 + threadIdx.x;
    if (g >= TOTE) return;
    int r = g / E_;
    int pos = atomicAdd(&g_cursor[r * N_ + dst_idx[g]], 1);
    g_srcsorted[pos] = src_idx[g];
}

// ------------- GAT aggregation: single pass, no max (logits tiny) ----------
__global__ void agg_k(const float* __restrict__ bias_g) {
    int gw = (blockIdx.x * 256 + threadIdx.x) >> 5;
    int lane = threadIdx.x & 31;
    if (gw >= TOTSEG) return;
    int r = (gw >= 2 * N_) ? 2 : (gw >= N_ ? 1 : 0);
    int n = gw - r * N_;
    int beg = g_rowptr[gw], end = g_rowptr[gw + 1];
    int h = lane >> 3;
    float er = ((const float*)g_er4)[((size_t)r * RPAD + n) * 4 + h];
    const float* elb = (const float*)g_el4 + (size_t)r * RPAD * 4;
    const float4* hs4 = (const float4*)(g_hs + (size_t)r * RPAD * 128);

    float4 acc = make_float4(0.f, 0.f, 0.f, 0.f);
    float ssum = 0.f;
    int s_next = (beg < end) ? g_srcsorted[beg] : 0;
    for (int i = beg; i < end; i++) {
        int s = s_next;
        if (i + 1 < end) s_next = g_srcsorted[i + 1];
        float e = __expf(lrelu(elb[s * 4 + h] + er));
        float4 hv = hs4[(size_t)s * 32 + lane];
        ssum += e;
        acc.x += e * hv.x; acc.y += e * hv.y;
        acc.z += e * hv.z; acc.w += e * hv.w;
    }
    float inv = 1.f / (ssum + 1e-9f);
    float4 bg = *(const float4*)(bias_g + r * 128 + lane * 4);
    float4 z;
    z.x = elu1(acc.x * inv + bg.x);
    z.y = elu1(acc.y * inv + bg.y);
    z.z = elu1(acc.z * inv + bg.z);
    z.w = elu1(acc.w * inv + bg.w);
    *(float4*)(g_z + ((size_t)r * RPAD + n) * 128 + lane * 4) = z;
}

// -------------------- combine (a computed in-kernel) -----------------------
__global__ void final_k(float* __restrict__ out, float* __restrict__ out_att) {
    float w0 = g_wsum[0] * (1.f / N_);
    float w1 = g_wsum[1] * (1.f / N_);
    float w2 = g_wsum[2] * (1.f / N_);
    float m = fmaxf(w0, fmaxf(w1, w2));
    float e0 = __expf(w0 - m), e1 = __expf(w1 - m), e2 = __expf(w2 - m);
    float inv = 1.f / (e0 + e1 + e2);
    float a0 = e0 * inv, a1 = e1 * inv, a2 = e2 * inv;

    size_t i = (size_t)blockIdx.x * 256 + threadIdx.x;
    if (i == 0) { out_att[0] = a0; out_att[1] = a1; out_att[2] = a2; }
    if (i >= (size_t)N_ * 32) return;
    size_t e = i * 4;
    float4 z0 = *(const float4*)(g_z + e);
    float4 z1 = *(const float4*)(g_z + (size_t)RPAD * 128 + e);
    float4 z2 = *(const float4*)(g_z + (size_t)2 * RPAD * 128 + e);
    float4 o;
    o.x = a0 * z0.x + a1 * z1.x + a2 * z2.x;
    o.y = a0 * z0.y + a1 * z1.y + a2 * z2.y;
    o.z = a0 * z0.z + a1 * z1.z + a2 * z2.z;
    o.w = a0 * z0.w + a1 * z1.w + a2 * z2.w;
    *(float4*)(out + e) = o;
}

// ----------------------------- launcher ------------------------------------
extern "C" void kernel_launch(void* const* d_in, const int* in_sizes, int n_in,
                              void* d_out, int out_size) {
    const float* dst_feat  = (const float*)d_in[0];
    const float* src_feats = (const float*)d_in[1];
    const int*   src_idx   = (const int*)d_in[2];
    const int*   dst_idx   = (const int*)d_in[3];
    const float* Wt_dst    = (const float*)d_in[4];
    const float* bt_dst    = (const float*)d_in[5];
    const float* Wt_src    = (const float*)d_in[6];
    const float* bt_src    = (const float*)d_in[7];
    const float* Wg        = (const float*)d_in[8];
    const float* attn_l    = (const float*)d_in[9];
    const float* bias_g    = (const float*)d_in[11];
    const float* attn_r    = (const float*)d_in[10];
    const float* W1        = (const float*)d_in[12];
    const float* b1        = (const float*)d_in[13];
    const float* W2        = (const float*)d_in[14];
    float* out = (float*)d_out;

    void *pWcs, *pbcs, *phs, *pz;
    cudaGetSymbolAddress(&pWcs, g_Wc_src);
    cudaGetSymbolAddress(&pbcs, g_bc_src);
    cudaGetSymbolAddress(&phs, g_hs);
    cudaGetSymbolAddress(&pz, g_z);

    cudaFuncSetAttribute(mma_gemm<0>, cudaFuncAttributeMaxDynamicSharedMemorySize, SMEM_MMA);
    cudaFuncSetAttribute(mma_gemm<1>, cudaFuncAttributeMaxDynamicSharedMemorySize, SMEM_MMA);

    p1_k<<<54 + NB_ZERO, 256>>>(Wt_src, Wt_dst, Wg, bt_src, bt_dst);
    p2_k<<<49, 256>>>(attn_r);

    count_k<<<(TOTE + 255) / 256, 256>>>(dst_idx);
    scan1_k<<<NB_SCAN, 256>>>();
    scan2_k<<<1, 32>>>();
    scan3_k<<<NB_SCAN, 256>>>();
    scatter_k<<<(TOTE + 255) / 256, 256>>>(dst_idx, src_idx);

    // hs = src @ Wc_src + bc  (bf16x3 tensor cores) + fused el epilogue
    mma_gemm<0><<<dim3(RPAD / 128, 3), 256, SMEM_MMA>>>(
        src_feats, N_, (long long)N_ * 128, (const float*)pWcs, 16384,
        (const float*)pbcs, 128, attn_l, 128, (float*)phs);

    attn_proj_er<<<(N_ + 7) / 8, 256>>>(dst_feat);

    agg_k<<<(TOTSEG + 7) / 8, 256>>>(bias_g);

    // wsum[r] = sum_n tanh(z@W1+b1)@W2  (bf16x3 tensor cores, fused reduce)
    mma_gemm<1><<<dim3(RPAD / 128, 3), 256, SMEM_MMA>>>(
        (const float*)pz, N_, (long long)RPAD * 128, W1, 0,
        b1, 0, W2, 0, nullptr);

    final_k<<<(N_ * 32 + 255) / 256, 256>>>(out, out + (size_t)N_ * 128);
}

// round 7
// speedup vs baseline: 1.9077x; 1.2333x over previous
#include <cuda_runtime.h>
#include <cuda_bf16.h>
#include <cuda_fp16.h>
#include <math.h>

#define N_ 100000
#define RPAD 100096
#define R_ 3
#define E_ 320000
#define TOTSEG (R_*N_)
#define TOTE (R_*E_)
#define NB_SCAN ((TOTSEG + 1023) / 1024)
#define NB_ZERO ((TOTSEG + 255) / 256)
#define WP 136
#define SMEM_MMA (2*128*WP*2 + 2*128*4)

// ----------------------------- device scratch ------------------------------
__device__ float g_Wc_src[R_*128*128];
__device__ float g_Wc_dst[R_*128*128];
__device__ float g_bc_src[R_*128];
__device__ float g_bc_dst[R_*128];
__device__ float g_V[R_*128*4];
__device__ float4 g_erb4[R_];
__device__ float g_hs[(size_t)R_*RPAD*128];
__device__ float g_z[(size_t)R_*RPAD*128];
__device__ __half g_z16[(size_t)R_*RPAD*128];
__device__ float4 g_el4[(size_t)R_*RPAD];
__device__ float4 g_er4[(size_t)R_*RPAD];
__device__ int   g_cnt[TOTSEG];
__device__ int   g_rowptr[TOTSEG + 1];
__device__ int   g_cursor[TOTSEG];
__device__ int   g_blksum[NB_SCAN];
__device__ int   g_srcsorted[TOTE];
__device__ float g_wsum[R_];

// ----------------------------- helpers -------------------------------------
__device__ __forceinline__ unsigned long long pk(float x, float y) {
    unsigned long long r;
    asm("mov.b64 %0, {%1, %2};" : "=l"(r) : "f"(x), "f"(y));
    return r;
}
__device__ __forceinline__ void fma2(unsigned long long& d, unsigned long long a,
                                     unsigned long long b) {
    asm("fma.rn.f32x2 %0, %1, %2, %0;" : "+l"(d) : "l"(a), "l"(b));
}
__device__ __forceinline__ float2 upk(unsigned long long v) {
    float2 f;
    asm("mov.b64 {%0, %1}, %2;" : "=f"(f.x), "=f"(f.y) : "l"(v));
    return f;
}
__device__ __forceinline__ float tanha(float x) {
    float y; asm("tanh.approx.f32 %0, %1;" : "=f"(y) : "f"(x)); return y;
}
__device__ __forceinline__ float lrelu(float x) { return x > 0.f ? x : 0.2f * x; }
__device__ __forceinline__ float elu1(float x)  { return x > 0.f ? x : (__expf(x) - 1.f); }

__device__ __forceinline__ void mma_bf16(float* c, const unsigned* a,
                                         unsigned b0, unsigned b1) {
    asm volatile(
        "mma.sync.aligned.m16n8k16.row.col.f32.bf16.bf16.f32 "
        "{%0,%1,%2,%3}, {%4,%5,%6,%7}, {%8,%9}, {%0,%1,%2,%3};"
        : "+f"(c[0]), "+f"(c[1]), "+f"(c[2]), "+f"(c[3])
        : "r"(a[0]), "r"(a[1]), "r"(a[2]), "r"(a[3]), "r"(b0), "r"(b1));
}
__device__ __forceinline__ void mma_f16(float* c, const unsigned* a,
                                        unsigned b0, unsigned b1) {
    asm volatile(
        "mma.sync.aligned.m16n8k16.row.col.f32.f16.f16.f32 "
        "{%0,%1,%2,%3}, {%4,%5,%6,%7}, {%8,%9}, {%0,%1,%2,%3};"
        : "+f"(c[0]), "+f"(c[1]), "+f"(c[2]), "+f"(c[3])
        : "r"(a[0]), "r"(a[1]), "r"(a[2]), "r"(a[3]), "r"(b0), "r"(b1));
}

// ---------------- P1: zero + weight GEMMs + combined biases ----------------
__global__ void __launch_bounds__(256) p1_k(const float* __restrict__ Wt_src,
                                            const float* __restrict__ Wt_dst,
                                            const float* __restrict__ Wg,
                                            const float* __restrict__ bt_src,
                                            const float* __restrict__ bt_dst) {
    int b = blockIdx.x;
    int tid = threadIdx.x;
    if (b >= 54) {
        int t = (b - 54) * 256 + tid;
        if (t < TOTSEG) g_cnt[t] = 0;
        if (t < R_) g_wsum[t] = 0.f;
        return;
    }
    if (b >= 6) {
        int gw = (b - 6) * 8 + (tid >> 5);
        int lane = tid & 31;
        if (gw >= R_ * 128) return;
        int r = gw >> 7, c = gw & 127;
        float s1 = 0.f, s2 = 0.f;
#pragma unroll
        for (int i = 0; i < 4; i++) {
            int h = lane + i * 32;
            float w = Wg[r * 16384 + h * 128 + c];
            s1 += bt_src[r * 128 + h] * w;
            s2 += bt_dst[h] * w;
        }
#pragma unroll
        for (int o = 16; o; o >>= 1) {
            s1 += __shfl_xor_sync(0xffffffffu, s1, o);
            s2 += __shfl_xor_sync(0xffffffffu, s2, o);
        }
        if (lane == 0) { g_bc_src[gw] = s1; g_bc_dst[gw] = s2; }
        return;
    }
    int r = b % 3;
    const float* Ar = (b < 3) ? (Wt_src + r * 16384) : Wt_dst;
    const float* Wr = Wg + r * 16384;
    float* Cr = ((b < 3) ? g_Wc_src : g_Wc_dst) + r * 16384;

    __shared__ __align__(16) float sA[16][132];
    __shared__ __align__(16) float sB[16][128];
    int tx = tid & 15, ty = tid >> 4;

    unsigned long long acc[8][4];
#pragma unroll
    for (int i = 0; i < 8; i++)
#pragma unroll
        for (int p = 0; p < 4; p++) acc[i][p] = 0ull;

    for (int kk = 0; kk < 128; kk += 16) {
#pragma unroll
        for (int l = 0; l < 2; l++) {
            int q = tid + l * 256;
            int row = q >> 2, ks = (q & 3) * 4;
            float4 v = *(const float4*)(Ar + (size_t)row * 128 + kk + ks);
            sA[ks + 0][row] = v.x; sA[ks + 1][row] = v.y;
            sA[ks + 2][row] = v.z; sA[ks + 3][row] = v.w;
        }
#pragma unroll
        for (int l = 0; l < 2; l++) {
            int q = tid + l * 256;
            int k = q >> 5, c = (q & 31) * 4;
            *(float4*)&sB[k][c] = *(const float4*)(Wr + (size_t)(kk + k) * 128 + c);
        }
        __syncthreads();
#pragma unroll
        for (int k = 0; k < 16; k++) {
            float4 a0 = *(const float4*)&sA[k][ty * 8];
            float4 a1 = *(const float4*)&sA[k][ty * 8 + 4];
            float4 b0 = *(const float4*)&sB[k][tx * 8];
            float4 b1v = *(const float4*)&sB[k][tx * 8 + 4];
            unsigned long long pb0 = pk(b0.x, b0.y), pb1 = pk(b0.z, b0.w);
            unsigned long long pb2 = pk(b1v.x, b1v.y), pb3 = pk(b1v.z, b1v.w);
            float av[8] = {a0.x, a0.y, a0.z, a0.w, a1.x, a1.y, a1.z, a1.w};
#pragma unroll
            for (int i = 0; i < 8; i++) {
                unsigned long long pa = pk(av[i], av[i]);
                fma2(acc[i][0], pa, pb0); fma2(acc[i][1], pa, pb1);
                fma2(acc[i][2], pa, pb2); fma2(acc[i][3], pa, pb3);
            }
        }
        __syncthreads();
    }
    int c0 = tx * 8;
#pragma unroll
    for (int i = 0; i < 8; i++) {
        int row = ty * 8 + i;
        float o[8];
#pragma unroll
        for (int p = 0; p < 4; p++) {
            float2 v = upk(acc[i][p]);
            o[2 * p] = v.x; o[2 * p + 1] = v.y;
        }
        *(float4*)(Cr + (size_t)row * 128 + c0) = make_float4(o[0], o[1], o[2], o[3]);
        *(float4*)(Cr + (size_t)row * 128 + c0 + 4) = make_float4(o[4], o[5], o[6], o[7]);
    }
}

// ---------------- P2: V projection + er bias (384 threads!) ----------------
__global__ void __launch_bounds__(384) p2_k(const float* __restrict__ attn_r) {
    int b = blockIdx.x;
    int tid = threadIdx.x;
    int lane = tid & 31;
    if (b == 32) {                      // erb: 12 warps (r,h)
        int w = tid >> 5;
        if (w >= 12) return;
        int r = w >> 2, h = w & 3;
        float v = g_bc_dst[r * 128 + h * 32 + lane] * attn_r[r * 128 + h * 32 + lane];
#pragma unroll
        for (int o = 16; o; o >>= 1) v += __shfl_xor_sync(0xffffffffu, v, o);
        if (lane == 0) ((float*)g_erb4)[r * 4 + h] = v;
        return;
    }
    int gw = b * 12 + (tid >> 5);
    if (gw >= R_ * 128) return;
    int r = gw >> 7, k = gw & 127;
    const float* Wcd = g_Wc_dst + r * 16384;
    const float* ar = attn_r + r * 128;
    float p[4];
#pragma unroll
    for (int h = 0; h < 4; h++)
        p[h] = Wcd[k * 128 + h * 32 + lane] * ar[h * 32 + lane];
#pragma unroll
    for (int o = 16; o; o >>= 1)
#pragma unroll
        for (int h = 0; h < 4; h++)
            p[h] += __shfl_xor_sync(0xffffffffu, p[h], o);
    if (lane == 0)
        *(float4*)&g_V[(r * 128 + k) * 4] = make_float4(p[0], p[1], p[2], p[3]);
}

// -------- hs GEMM: bf16x3, warp-per-16-rows (A loaded once) + el fused -----
__global__ void __launch_bounds__(256)
mma_hs(const float* __restrict__ Afp,
       const float* __restrict__ bias,
       const float* __restrict__ attn_l,
       float* __restrict__ Cout) {
    extern __shared__ char dsm[];
    __nv_bfloat16* sWhi = (__nv_bfloat16*)dsm;
    __nv_bfloat16* sWlo = sWhi + 128 * WP;
    float* sBias = (float*)(sWlo + 128 * WP);
    float* sAux  = sBias + 128;

    int r = blockIdx.y;
    int tid = threadIdx.x;
    const float* Wr = g_Wc_src + (size_t)r * 16384;
    for (int idx = tid; idx < 16384; idx += 256) {
        int k = idx >> 7, n = idx & 127;
        float w = Wr[idx];
        __nv_bfloat16 h = __float2bfloat16(w);
        sWhi[n * WP + k] = h;
        sWlo[n * WP + k] = __float2bfloat16(w - __bfloat162float(h));
    }
    if (tid < 128) {
        sBias[tid] = bias[r * 128 + tid];
        sAux[tid]  = attn_l[r * 128 + tid];
    }
    __syncthreads();

    int lane = tid & 31, wid = tid >> 5;
    int g = lane >> 2, t = lane & 3;
    int rbase = blockIdx.x * 128 + wid * 16;
    int r0 = rbase + g, r1 = rbase + 8 + g;
    const float* af0 = Afp + (size_t)r * N_ * 128 + (size_t)(r0 < N_ ? r0 : N_ - 1) * 128;
    const float* af1 = Afp + (size_t)r * N_ * 128 + (size_t)(r1 < N_ ? r1 : N_ - 1) * 128;

    float acc[16][4];
#pragma unroll
    for (int nt = 0; nt < 16; nt++)
#pragma unroll
        for (int q = 0; q < 4; q++) acc[nt][q] = 0.f;

    for (int k0 = 0; k0 < 128; k0 += 16) {
        unsigned ah[4], al[4];
#pragma unroll
        for (int jj = 0; jj < 4; jj++) {
            const float* ap = (jj & 1) ? af1 : af0;
            int ko = k0 + t * 2 + (jj >> 1) * 8;
            float2 v = *(const float2*)(ap + ko);
            __nv_bfloat162 h2 = __floats2bfloat162_rn(v.x, v.y);
            float lx = v.x - __low2float(h2);
            float ly = v.y - __high2float(h2);
            __nv_bfloat162 l2 = __floats2bfloat162_rn(lx, ly);
            ah[jj] = *(unsigned*)&h2;
            al[jj] = *(unsigned*)&l2;
        }
#pragma unroll
        for (int nt = 0; nt < 16; nt++) {
            int n = nt * 8 + g;
            const __nv_bfloat16* bp = &sWhi[n * WP + k0 + t * 2];
            unsigned bh0 = *(const unsigned*)bp;
            unsigned bh1 = *(const unsigned*)(bp + 8);
            const __nv_bfloat16* bq = &sWlo[n * WP + k0 + t * 2];
            unsigned bl0 = *(const unsigned*)bq;
            unsigned bl1 = *(const unsigned*)(bq + 8);
            mma_bf16(acc[nt], ah, bh0, bh1);
            mma_bf16(acc[nt], ah, bl0, bl1);
            mma_bf16(acc[nt], al, bh0, bh1);
        }
    }

    float* Cr = Cout + (size_t)r * RPAD * 128;
    float elp[2][4];
#pragma unroll
    for (int q = 0; q < 4; q++) { elp[0][q] = 0.f; elp[1][q] = 0.f; }
#pragma unroll
    for (int nt = 0; nt < 16; nt++) {
        int n0 = nt * 8 + t * 2;
        float b0 = sBias[n0], b1v = sBias[n0 + 1];
        float a0 = sAux[n0],  a1 = sAux[n0 + 1];
        float v00 = acc[nt][0] + b0, v01 = acc[nt][1] + b1v;
        float v10 = acc[nt][2] + b0, v11 = acc[nt][3] + b1v;
        *(float2*)&Cr[(size_t)r0 * 128 + n0] = make_float2(v00, v01);
        *(float2*)&Cr[(size_t)r1 * 128 + n0] = make_float2(v10, v11);
        int h = nt >> 2;
        elp[0][h] += v00 * a0 + v01 * a1;
        elp[1][h] += v10 * a0 + v11 * a1;
    }
#pragma unroll
    for (int j = 0; j < 2; j++)
#pragma unroll
        for (int h = 0; h < 4; h++) {
            float v = elp[j][h];
            v += __shfl_xor_sync(0xffffffffu, v, 1);
            v += __shfl_xor_sync(0xffffffffu, v, 2);
            elp[j][h] = v;
        }
    if (t == 0) {
        float4* elf = g_el4 + (size_t)r * RPAD;
        elf[r0] = make_float4(elp[0][0], elp[0][1], elp[0][2], elp[0][3]);
        elf[r1] = make_float4(elp[1][0], elp[1][1], elp[1][2], elp[1][3]);
    }
}

// -------- semantic GEMM: fp16 single-mma, fused tanh*W2 reduce -------------
__global__ void __launch_bounds__(256)
mma_sem(const __half* __restrict__ A16,
        const float* __restrict__ W1,
        const float* __restrict__ b1,
        const float* __restrict__ W2) {
    __shared__ __half sW[128 * WP];
    __shared__ float sBias[128];
    __shared__ float sW2[128];
    __shared__ float sred[8];

    int r = blockIdx.y;
    int tid = threadIdx.x;
    for (int idx = tid; idx < 16384; idx += 256) {
        int k = idx >> 7, n = idx & 127;
        sW[n * WP + k] = __float2half(W1[idx]);
    }
    if (tid < 128) { sBias[tid] = b1[tid]; sW2[tid] = W2[tid]; }
    __syncthreads();

    int lane = tid & 31, wid = tid >> 5;
    int g = lane >> 2, t = lane & 3;
    int rbase = blockIdx.x * 128 + wid * 16;
    int r0 = rbase + g, r1 = rbase + 8 + g;
    const __half* a0p = A16 + ((size_t)r * RPAD + r0) * 128;
    const __half* a1p = A16 + ((size_t)r * RPAD + r1) * 128;

    float acc[16][4];
#pragma unroll
    for (int nt = 0; nt < 16; nt++)
#pragma unroll
        for (int q = 0; q < 4; q++) acc[nt][q] = 0.f;

    for (int k0 = 0; k0 < 128; k0 += 16) {
        unsigned a[4];
        a[0] = *(const unsigned*)(a0p + k0 + t * 2);
        a[1] = *(const unsigned*)(a1p + k0 + t * 2);
        a[2] = *(const unsigned*)(a0p + k0 + t * 2 + 8);
        a[3] = *(const unsigned*)(a1p + k0 + t * 2 + 8);
#pragma unroll
        for (int nt = 0; nt < 16; nt++) {
            int n = nt * 8 + g;
            const __half* bp = &sW[n * WP + k0 + t * 2];
            unsigned b0 = *(const unsigned*)bp;
            unsigned b1u = *(const unsigned*)(bp + 8);
            mma_f16(acc[nt], a, b0, b1u);
        }
    }

    float s = 0.f;
#pragma unroll
    for (int nt = 0; nt < 16; nt++) {
        int n0 = nt * 8 + t * 2;
        float b0 = sBias[n0], b1v = sBias[n0 + 1];
        float w0 = sW2[n0],   w1 = sW2[n0 + 1];
        if (r0 < N_)
            s += tanha(acc[nt][0] + b0) * w0 + tanha(acc[nt][1] + b1v) * w1;
        if (r1 < N_)
            s += tanha(acc[nt][2] + b0) * w0 + tanha(acc[nt][3] + b1v) * w1;
    }
#pragma unroll
    for (int o = 16; o; o >>= 1) s += __shfl_xor_sync(0xffffffffu, s, o);
    if (lane == 0) sred[wid] = s;
    __syncthreads();
    if (tid == 0) {
        float tt = 0.f;
#pragma unroll
        for (int j = 0; j < 8; j++) tt += sred[j];
        atomicAdd(&g_wsum[r], tt);
    }
}

// ----------------- er per node (warp per node) -----------------------------
__global__ void attn_proj_er(const float* __restrict__ dst_feat) {
    int gw = (blockIdx.x * 256 + threadIdx.x) >> 5;
    int lane = threadIdx.x & 31;
    if (gw >= N_) return;
    float4 dv = *(const float4*)(dst_feat + (size_t)gw * 128 + lane * 4);
    float dvv[4] = {dv.x, dv.y, dv.z, dv.w};
#pragma unroll
    for (int r = 0; r < R_; r++) {
        const float4* V4 = (const float4*)(g_V + r * 512);
        float4 aD = make_float4(0, 0, 0, 0);
#pragma unroll
        for (int i = 0; i < 4; i++) {
            float4 w = V4[lane * 4 + i];
            aD.x += dvv[i] * w.x; aD.y += dvv[i] * w.y;
            aD.z += dvv[i] * w.z; aD.w += dvv[i] * w.w;
        }
#pragma unroll
        for (int o = 16; o; o >>= 1) {
            aD.x += __shfl_xor_sync(0xffffffffu, aD.x, o);
            aD.y += __shfl_xor_sync(0xffffffffu, aD.y, o);
            aD.z += __shfl_xor_sync(0xffffffffu, aD.z, o);
            aD.w += __shfl_xor_sync(0xffffffffu, aD.w, o);
        }
        if (lane == 0) {
            float4 rb = g_erb4[r];
            g_er4[(size_t)r * RPAD + gw] =
                make_float4(aD.x + rb.x, aD.y + rb.y, aD.z + rb.z, aD.w + rb.w);
        }
    }
}

// ----------------------------- CSR build -----------------------------------
__global__ void count_k(const int* __restrict__ dst_idx) {
    int g = blockIdx.x * 256 + threadIdx.x;
    if (g >= TOTE) return;
    int r = g / E_;
    atomicAdd(&g_cnt[r * N_ + dst_idx[g]], 1);
}
__global__ void scan1_k() {
    __shared__ int sh[256];
    int b = blockIdx.x, t = threadIdx.x;
    int base = b * 1024 + t * 4;
    int v[4];
#pragma unroll
    for (int i = 0; i < 4; i++) v[i] = (base + i < TOTSEG) ? g_cnt[base + i] : 0;
    int s = v[0] + v[1] + v[2] + v[3];
    sh[t] = s;
    __syncthreads();
    for (int o = 1; o < 256; o <<= 1) {
        int x = (t >= o) ? sh[t - o] : 0;
        __syncthreads();
        sh[t] += x;
        __syncthreads();
    }
    int p = sh[t] - s;
#pragma unroll
    for (int i = 0; i < 4; i++) {
        if (base + i < TOTSEG) g_rowptr[base + i] = p;
        p += v[i];
    }
    if (t == 255) g_blksum[b] = sh[255];
}
// merged scan2+scan3: each block computes its own offset from blksums
__global__ void scan23_k() {
    __shared__ int sh[256];
    int b = blockIdx.x, t = threadIdx.x;
    int part = 0;
    for (int i = t; i < b; i += 256) part += g_blksum[i];
    sh[t] = part;
    __syncthreads();
    for (int o = 128; o; o >>= 1) {
        if (t < o) sh[t] += sh[t + o];
        __syncthreads();
    }
    int off = sh[0];
    int base = b * 1024 + t * 4;
#pragma unroll
    for (int i = 0; i < 4; i++) {
        int idx = base + i;
        if (idx < TOTSEG) {
            int val = g_rowptr[idx] + off;
            g_rowptr[idx] = val;
            g_cursor[idx] = val;
        }
    }
    if (b == 0 && t == 0) g_rowptr[TOTSEG] = TOTE;
}
__global__ void scatter_k(const int* __restrict__ dst_idx,
                          const int* __restrict__ src_idx) {
    int g = blockIdx.x * 256 + threadIdx.x;
    if (g >= TOTE) return;
    int r = g / E_;
    int pos = atomicAdd(&g_cursor[r * N_ + dst_idx[g]], 1);
    g_srcsorted[pos] = src_idx[g];
}

// ------------- GAT aggregation: single pass; writes z fp32 + fp16 ----------
__global__ void agg_k(const float* __restrict__ bias_g) {
    int gw = (blockIdx.x * 256 + threadIdx.x) >> 5;
    int lane = threadIdx.x & 31;
    if (gw >= TOTSEG) return;
    int r = (gw >= 2 * N_) ? 2 : (gw >= N_ ? 1 : 0);
    int n = gw - r * N_;
    int beg = g_rowptr[gw], end = g_rowptr[gw + 1];
    int h = lane >> 3;
    float er = ((const float*)g_er4)[((size_t)r * RPAD + n) * 4 + h];
    const float* elb = (const float*)g_el4 + (size_t)r * RPAD * 4;
    const float4* hs4 = (const float4*)(g_hs + (size_t)r * RPAD * 128);

    float4 acc = make_float4(0.f, 0.f, 0.f, 0.f);
    float ssum = 0.f;
    int s_next = (beg < end) ? g_srcsorted[beg] : 0;
    for (int i = beg; i < end; i++) {
        int s = s_next;
        if (i + 1 < end) s_next = g_srcsorted[i + 1];
        float e = __expf(lrelu(elb[s * 4 + h] + er));
        float4 hv = hs4[(size_t)s * 32 + lane];
        ssum += e;
        acc.x += e * hv.x; acc.y += e * hv.y;
        acc.z += e * hv.z; acc.w += e * hv.w;
    }
    float inv = 1.f / (ssum + 1e-9f);
    float4 bg = *(const float4*)(bias_g + r * 128 + lane * 4);
    float4 z;
    z.x = elu1(acc.x * inv + bg.x);
    z.y = elu1(acc.y * inv + bg.y);
    z.z = elu1(acc.z * inv + bg.z);
    z.w = elu1(acc.w * inv + bg.w);
    size_t zo = ((size_t)r * RPAD + n) * 128 + lane * 4;
    *(float4*)(g_z + zo) = z;
    __half2 hA = __floats2half2_rn(z.x, z.y);
    __half2 hB = __floats2half2_rn(z.z, z.w);
    *(uint2*)(g_z16 + zo) = make_uint2(*(unsigned*)&hA, *(unsigned*)&hB);
}

// -------------------- combine (a computed in-kernel) -----------------------
__global__ void final_k(float* __restrict__ out, float* __restrict__ out_att) {
    float w0 = g_wsum[0] * (1.f / N_);
    float w1 = g_wsum[1] * (1.f / N_);
    float w2 = g_wsum[2] * (1.f / N_);
    float m = fmaxf(w0, fmaxf(w1, w2));
    float e0 = __expf(w0 - m), e1 = __expf(w1 - m), e2 = __expf(w2 - m);
    float inv = 1.f / (e0 + e1 + e2);
    float a0 = e0 * inv, a1 = e1 * inv, a2 = e2 * inv;

    size_t i = (size_t)blockIdx.x * 256 + threadIdx.x;
    if (i == 0) { out_att[0] = a0; out_att[1] = a1; out_att[2] = a2; }
    if (i >= (size_t)N_ * 32) return;
    size_t e = i * 4;
    float4 z0 = *(const float4*)(g_z + e);
    float4 z1 = *(const float4*)(g_z + (size_t)RPAD * 128 + e);
    float4 z2 = *(const float4*)(g_z + (size_t)2 * RPAD * 128 + e);
    float4 o;
    o.x = a0 * z0.x + a1 * z1.x + a2 * z2.x;
    o.y = a0 * z0.y + a1 * z1.y + a2 * z2.y;
    o.z = a0 * z0.z + a1 * z1.z + a2 * z2.z;
    o.w = a0 * z0.w + a1 * z1.w + a2 * z2.w;
    *(float4*)(out + e) = o;
}

// ----------------------------- launcher ------------------------------------
extern "C" void kernel_launch(void* const* d_in, const int* in_sizes, int n_in,
                              void* d_out, int out_size) {
    const float* dst_feat  = (const float*)d_in[0];
    const float* src_feats = (const float*)d_in[1];
    const int*   src_idx   = (const int*)d_in[2];
    const int*   dst_idx   = (const int*)d_in[3];
    const float* Wt_dst    = (const float*)d_in[4];
    const float* bt_dst    = (const float*)d_in[5];
    const float* Wt_src    = (const float*)d_in[6];
    const float* bt_src    = (const float*)d_in[7];
    const float* Wg        = (const float*)d_in[8];
    const float* attn_l    = (const float*)d_in[9];
    const float* attn_r    = (const float*)d_in[10];
    const float* bias_g    = (const float*)d_in[11];
    const float* W1        = (const float*)d_in[12];
    const float* b1        = (const float*)d_in[13];
    const float* W2        = (const float*)d_in[14];
    float* out = (float*)d_out;

    void *pbcs, *phs, *pz16;
    cudaGetSymbolAddress(&pbcs, g_bc_src);
    cudaGetSymbolAddress(&phs, g_hs);
    cudaGetSymbolAddress(&pz16, g_z16);

    cudaFuncSetAttribute(mma_hs, cudaFuncAttributeMaxDynamicSharedMemorySize, SMEM_MMA);

    p1_k<<<54 + NB_ZERO, 256>>>(Wt_src, Wt_dst, Wg, bt_src, bt_dst);
    p2_k<<<33, 384>>>(attn_r);
    count_k<<<(TOTE + 255) / 256, 256>>>(dst_idx);

    // profiled slot (index 3): the heavy hs GEMM
    mma_hs<<<dim3(RPAD / 128, 3), 256, SMEM_MMA>>>(
        src_feats, (const float*)pbcs, attn_l, (float*)phs);

    scan1_k<<<NB_SCAN, 256>>>();
    scan23_k<<<NB_SCAN, 256>>>();
    scatter_k<<<(TOTE + 255) / 256, 256>>>(dst_idx, src_idx);

    attn_proj_er<<<(N_ + 7) / 8, 256>>>(dst_feat);

    agg_k<<<(TOTSEG + 7) / 8, 256>>>(bias_g);

    mma_sem<<<dim3(RPAD / 128, 3), 256>>>((const __half*)pz16, W1, b1, W2);

    final_k<<<(N_ * 32 + 255) / 256, 256>>>(out, out + (size_t)N_ * 128);
}